// round 8
// baseline (speedup 1.0000x reference)
#include <cuda_runtime.h>
#include <cuda_bf16.h>
#include <cuda_fp16.h>
#include <math.h>
#include <stdint.h>

// Problem constants
#define BSZ 2
#define LSEQ 2048
#define EMB 1024
#define NH 16
#define DH 64
#define BH 32          // BSZ*NH
#define M1 4096        // BSZ*LSEQ
#define N1 3072        // 3*EMB

// Scratch (allocation-free)
__device__ __nv_bfloat16 g_xh[M1*EMB],  g_xl[M1*EMB];
__device__ __nv_bfloat16 g_wih[N1*EMB], g_wil[N1*EMB];
__device__ __nv_bfloat16 g_woh[EMB*EMB],g_wol[EMB*EMB];
__device__ __nv_bfloat16 g_ch[M1*EMB],  g_cl[M1*EMB];
// attention operands in fp16 (q full precision hi/lo, k/v hi only)
__device__ __half g_qh[BH*LSEQ*DH], g_ql[BH*LSEQ*DH];
__device__ __half g_kh[BH*LSEQ*DH];
__device__ __half g_vh[BH*LSEQ*DH];

// ---------------------------------------------------------------------------
// PTX helpers
// ---------------------------------------------------------------------------
__device__ __forceinline__ uint32_t smem_u32(const void* p) {
    return (uint32_t)__cvta_generic_to_shared(p);
}
__device__ __forceinline__ void ldm_x4(uint32_t& a0, uint32_t& a1,
                                       uint32_t& a2, uint32_t& a3, uint32_t addr) {
    asm volatile("ldmatrix.sync.aligned.m8n8.x4.shared.b16 {%0,%1,%2,%3},[%4];\n"
                 : "=r"(a0), "=r"(a1), "=r"(a2), "=r"(a3) : "r"(addr));
}
__device__ __forceinline__ void ldm_x4_t(uint32_t& a0, uint32_t& a1,
                                         uint32_t& a2, uint32_t& a3, uint32_t addr) {
    asm volatile("ldmatrix.sync.aligned.m8n8.x4.trans.shared.b16 {%0,%1,%2,%3},[%4];\n"
                 : "=r"(a0), "=r"(a1), "=r"(a2), "=r"(a3) : "r"(addr));
}
// bf16 mma
__device__ __forceinline__ void mma16816(float* c, const uint32_t* a,
                                         uint32_t b0, uint32_t b1) {
    asm volatile("mma.sync.aligned.m16n8k16.row.col.f32.bf16.bf16.f32 "
                 "{%0,%1,%2,%3},{%4,%5,%6,%7},{%8,%9},{%0,%1,%2,%3};\n"
                 : "+f"(c[0]), "+f"(c[1]), "+f"(c[2]), "+f"(c[3])
                 : "r"(a[0]), "r"(a[1]), "r"(a[2]), "r"(a[3]), "r"(b0), "r"(b1));
}
// fp16 mma (fp32 accum)
__device__ __forceinline__ void mma16816h(float* c, const uint32_t* a,
                                          uint32_t b0, uint32_t b1) {
    asm volatile("mma.sync.aligned.m16n8k16.row.col.f32.f16.f16.f32 "
                 "{%0,%1,%2,%3},{%4,%5,%6,%7},{%8,%9},{%0,%1,%2,%3};\n"
                 : "+f"(c[0]), "+f"(c[1]), "+f"(c[2]), "+f"(c[3])
                 : "r"(a[0]), "r"(a[1]), "r"(a[2]), "r"(a[3]), "r"(b0), "r"(b1));
}
__device__ __forceinline__ void cp16(void* smem_ptr, const void* gptr) {
    asm volatile("cp.async.cg.shared.global [%0], [%1], 16;\n"
                 :: "r"(smem_u32(smem_ptr)), "l"(gptr));
}
__device__ __forceinline__ void cp_commit() {
    asm volatile("cp.async.commit_group;\n");
}
__device__ __forceinline__ void cp_wait0() {
    asm volatile("cp.async.wait_group 0;\n");
}
__device__ __forceinline__ uint32_t packbf(float lo, float hi) {
    uint32_t r;
    asm("cvt.rn.bf16x2.f32 %0, %1, %2;" : "=r"(r) : "f"(hi), "f"(lo));
    return r;
}
__device__ __forceinline__ void pack_hilo(float v0, float v1,
                                          uint32_t& ph, uint32_t& pl) {
    ph = packbf(v0, v1);
    __nv_bfloat162 h = *(__nv_bfloat162*)&ph;
    pl = packbf(v0 - __bfloat162float(h.x), v1 - __bfloat162float(h.y));
}
// fp16 pack: v0 -> low half, v1 -> high half
__device__ __forceinline__ uint32_t packh(float v0, float v1) {
    __half2 h = __floats2half2_rn(v0, v1);
    return *(uint32_t*)&h;
}
__device__ __forceinline__ void pack_hilo_h(float v0, float v1,
                                            uint32_t& ph, uint32_t& pl) {
    ph = packh(v0, v1);
    __half2 h = *(__half2*)&ph;
    pl = packh(v0 - __half2float(h.x), v1 - __half2float(h.y));
}

// ---------------------------------------------------------------------------
// Prep: fp32 -> bf16 hi/lo split
// ---------------------------------------------------------------------------
__global__ __launch_bounds__(256)
void cvt_hilo(const float* __restrict__ src, int sel, int n4)
{
    int i = blockIdx.x * 256 + threadIdx.x;
    if (i >= n4) return;
    __nv_bfloat16 *dh, *dl;
    if (sel == 0)      { dh = g_xh;  dl = g_xl;  }
    else if (sel == 1) { dh = g_wih; dl = g_wil; }
    else               { dh = g_woh; dl = g_wol; }
    float4 v = ((const float4*)src)[i];
    uint32_t h01, l01, h23, l23;
    pack_hilo(v.x, v.y, h01, l01);
    pack_hilo(v.z, v.w, h23, l23);
    ((uint32_t*)dh)[2*i]   = h01;  ((uint32_t*)dh)[2*i+1] = h23;
    ((uint32_t*)dl)[2*i]   = l01;  ((uint32_t*)dl)[2*i+1] = l23;
}

// ---------------------------------------------------------------------------
// GEMM: C[M,N] = A @ W^T + bias. Split-bf16 3-pass mma, cp.async double buffer.
// BM=128, BN=128, BK=32, 256 threads (8 warps: 4m x 2n, warp = 32m x 64n).
// MODE 0: A=g_x*, W=g_wi*; epilogue -> fp16: q hi/lo (UNSCALED), k hi, v hi
// MODE 1: A=g_c*, W=g_wo*; epilogue writes fp32 C row-major
// ---------------------------------------------------------------------------
#define GST 40
#define GARR 5120           // 128*GST
#define GSTAGE 20480        // 4 arrays per stage
#define GEMM_SMEM (2*GSTAGE*2)  // bytes = 81920

template<int MODE>
__global__ __launch_bounds__(256, 2)
void gemm_mma(const float* __restrict__ bias, float* __restrict__ Cout)
{
    extern __shared__ __nv_bfloat16 smg[];
    const int tid = threadIdx.x, lane = tid & 31, w = tid >> 5;
    const int wm = w >> 1, wn = w & 1;
    const int m0 = blockIdx.y * 128, n0 = blockIdx.x * 128;

    const __nv_bfloat16* Ahg = (MODE == 0) ? g_xh  : g_ch;
    const __nv_bfloat16* Alg = (MODE == 0) ? g_xl  : g_cl;
    const __nv_bfloat16* Whg = (MODE == 0) ? g_wih : g_woh;
    const __nv_bfloat16* Wlg = (MODE == 0) ? g_wil : g_wol;

    const int lr = tid >> 1;            // 0..127
    const int lq = (tid & 1) * 16;      // elem offset 0/16
    const __nv_bfloat16* pAh = Ahg + (size_t)(m0 + lr) * 1024 + lq;
    const __nv_bfloat16* pAl = Alg + (size_t)(m0 + lr) * 1024 + lq;
    const __nv_bfloat16* pWh = Whg + (size_t)(n0 + lr) * 1024 + lq;
    const __nv_bfloat16* pWl = Wlg + (size_t)(n0 + lr) * 1024 + lq;

    auto load_stage = [&](int st, int k0) {
        __nv_bfloat16* b = smg + st * GSTAGE + lr * GST + lq;
        cp16(b,            pAh + k0); cp16(b + 8,          pAh + k0 + 8);
        cp16(b + GARR,     pAl + k0); cp16(b + GARR + 8,   pAl + k0 + 8);
        cp16(b + 2*GARR,   pWh + k0); cp16(b + 2*GARR + 8, pWh + k0 + 8);
        cp16(b + 3*GARR,   pWl + k0); cp16(b + 3*GARR + 8, pWl + k0 + 8);
        cp_commit();
    };

    float c[2][8][4];
#pragma unroll
    for (int a = 0; a < 2; a++)
#pragma unroll
        for (int b = 0; b < 8; b++)
#pragma unroll
            for (int d = 0; d < 4; d++) c[a][b][d] = 0.f;

    load_stage(0, 0);

    for (int it = 0; it < 32; it++) {
        cp_wait0();
        __syncthreads();
        if (it < 31) load_stage((it + 1) & 1, (it + 1) * 32);

        __nv_bfloat16* Ah = smg + (it & 1) * GSTAGE;
        __nv_bfloat16* Al = Ah + GARR;
        __nv_bfloat16* Wh = Ah + 2*GARR;
        __nv_bfloat16* Wl = Ah + 3*GARR;

#pragma unroll
        for (int kk = 0; kk < 2; kk++) {
            uint32_t aH[2][4], aL[2][4];
#pragma unroll
            for (int mt = 0; mt < 2; mt++) {
                int row = wm * 32 + mt * 16 + (lane & 15);
                int kof = kk * 16 + ((lane >> 4) << 3);
                ldm_x4(aH[mt][0], aH[mt][1], aH[mt][2], aH[mt][3],
                       smem_u32(&Ah[row * GST + kof]));
                ldm_x4(aL[mt][0], aL[mt][1], aL[mt][2], aL[mt][3],
                       smem_u32(&Al[row * GST + kof]));
            }
#pragma unroll
            for (int np = 0; np < 4; np++) {
                int row = wn * 64 + np * 16 + ((lane >> 4) << 3) + (lane & 7);
                int kof = kk * 16 + ((lane >> 3) & 1) * 8;
                uint32_t bh0, bh1, bh2, bh3, bl0, bl1, bl2, bl3;
                ldm_x4(bh0, bh1, bh2, bh3, smem_u32(&Wh[row * GST + kof]));
                ldm_x4(bl0, bl1, bl2, bl3, smem_u32(&Wl[row * GST + kof]));
                mma16816(c[0][2*np],   aH[0], bh0, bh1);
                mma16816(c[0][2*np+1], aH[0], bh2, bh3);
                mma16816(c[1][2*np],   aH[1], bh0, bh1);
                mma16816(c[1][2*np+1], aH[1], bh2, bh3);
                mma16816(c[0][2*np],   aH[0], bl0, bl1);
                mma16816(c[0][2*np+1], aH[0], bl2, bl3);
                mma16816(c[1][2*np],   aH[1], bl0, bl1);
                mma16816(c[1][2*np+1], aH[1], bl2, bl3);
                mma16816(c[0][2*np],   aL[0], bh0, bh1);
                mma16816(c[0][2*np+1], aL[0], bh2, bh3);
                mma16816(c[1][2*np],   aL[1], bh0, bh1);
                mma16816(c[1][2*np+1], aL[1], bh2, bh3);
            }
        }
    }

    // Epilogue
    const int rA = lane >> 2, colq = (lane & 3) * 2;
#pragma unroll
    for (int mt = 0; mt < 2; mt++) {
#pragma unroll
        for (int np = 0; np < 4; np++) {
#pragma unroll
            for (int cc = 0; cc < 2; cc++) {
                int n = n0 + wn * 64 + np * 16 + cc * 8 + colq;
                int mrow = m0 + wm * 32 + mt * 16 + rA;
                float bv0 = bias[n], bv1 = bias[n + 1];
                float* cp = c[mt][2*np + cc];
                float v0 = cp[0] + bv0, v1 = cp[1] + bv1;
                float v2 = cp[2] + bv0, v3 = cp[3] + bv1;
                if (MODE == 0) {
                    int which = n >> 10;
                    int e = n & 1023, hh = e >> 6, d = e & 63;
                    int b = mrow >> 11;
                    size_t dA = (((size_t)(b * NH + hh)) * LSEQ + (mrow & 2047)) * DH + d;
                    size_t dB = dA + 8 * DH;
                    if (which == 0) {
                        // q: full precision fp16 hi/lo (no pre-scale)
                        uint32_t h01, l01, h23, l23;
                        pack_hilo_h(v0, v1, h01, l01);
                        pack_hilo_h(v2, v3, h23, l23);
                        *(uint32_t*)(g_qh + dA) = h01;
                        *(uint32_t*)(g_ql + dA) = l01;
                        *(uint32_t*)(g_qh + dB) = h23;
                        *(uint32_t*)(g_ql + dB) = l23;
                    } else {
                        __half* dst = (which == 1) ? g_kh : g_vh;
                        *(uint32_t*)(dst + dA) = packh(v0, v1);
                        *(uint32_t*)(dst + dB) = packh(v2, v3);
                    }
                } else {
                    *(float2*)(Cout + (size_t)mrow * EMB + n) = make_float2(v0, v1);
                    *(float2*)(Cout + (size_t)(mrow + 8) * EMB + n) = make_float2(v2, v3);
                }
            }
        }
    }
}

// ---------------------------------------------------------------------------
// Flash attention, fp16 2-pass: S = 0.125*((Qh+Ql)·Kh + 8*bias);
// O += (Ph+Pl)·Vh. K and V carry hi only (rounding err 2^-12 each).
// K/V double-buffered via cp.async. Grid (L/128, BH), 256 thr, 2 CTAs/SM.
// ---------------------------------------------------------------------------
#define AST 72
#define KARR 4608          // 64*AST
#define KSTAGE 9216        // 2 arrays (Kh, Vh)
#define ATTN_SMEM 73728    // (2*9216 Q + 2*9216 KV) * 2B

__global__ __launch_bounds__(256, 2)
void attn_mma(const float* __restrict__ keb)
{
    extern __shared__ __half sma[];
    __half* Qh = sma;
    __half* Ql = sma + 9216;
    __half* KVbase = sma + 18432;

    const int tid = threadIdx.x, lane = tid & 31, w = tid >> 5;
    const int bh = blockIdx.y;
    const int q0 = blockIdx.x * 128;
    const size_t hb = (size_t)bh * LSEQ * DH;
    const float* Bg = keb + (size_t)bh * LSEQ * LSEQ;

    const int lr = tid >> 2;           // 0..63
    const int lq = (tid & 3) * 16;     // 0,16,32,48
    const __half* pKh = g_kh + hb + (size_t)lr * 64 + lq;
    const __half* pVh = g_vh + hb + (size_t)lr * 64 + lq;

    auto load_kv = [&](int st, int k0) {
        __half* b = KVbase + st * KSTAGE + lr * AST + lq;
        size_t off = (size_t)k0 * 64;
        cp16(b,          pKh + off); cp16(b + 8,        pKh + off + 8);
        cp16(b + KARR,   pVh + off); cp16(b + KARR + 8, pVh + off + 8);
        cp_commit();
    };

    load_kv(0, 0);

    // Q tile -> smem (fp16 hi/lo)
#pragma unroll
    for (int i = 0; i < 4; i++) {
        int id = tid + i * 256;
        int r = id >> 3, c8 = (id & 7) * 8;
        size_t src = hb + (size_t)(q0 + r) * DH + c8;
        *(uint4*)&Qh[r * AST + c8] = *(const uint4*)(g_qh + src);
        *(uint4*)&Ql[r * AST + c8] = *(const uint4*)(g_ql + src);
    }
    __syncthreads();

    uint32_t qH[4][4], qL[4][4];
#pragma unroll
    for (int kk = 0; kk < 4; kk++) {
        int row = w * 16 + (lane & 15);
        int kof = kk * 16 + ((lane >> 4) << 3);
        ldm_x4(qH[kk][0], qH[kk][1], qH[kk][2], qH[kk][3], smem_u32(&Qh[row * AST + kof]));
        ldm_x4(qL[kk][0], qL[kk][1], qL[kk][2], qL[kk][3], smem_u32(&Ql[row * AST + kof]));
    }

    float o[8][4];
#pragma unroll
    for (int j = 0; j < 8; j++)
#pragma unroll
        for (int d = 0; d < 4; d++) o[j][d] = 0.f;
    float mA = -INFINITY, mB = -INFINITY, lA = 0.f, lB = 0.f;

    const int rA = lane >> 2, colq = (lane & 3) * 2;
    const int qrowA = q0 + w * 16 + rA;
    const float* Br0 = Bg + (size_t)qrowA * LSEQ + colq;
    const float* Br1 = Bg + (size_t)(qrowA + 8) * LSEQ + colq;

    for (int it = 0; it < 32; it++) {
        const int k0 = it * 64;

        // S init = 8*bias (scores scaled by 0.125 after mma => net +bias)
        float s[8][4];
#pragma unroll
        for (int j = 0; j < 8; j++) {
            float2 b0 = *(const float2*)(Br0 + k0 + j * 8);
            float2 b1 = *(const float2*)(Br1 + k0 + j * 8);
            s[j][0] = 8.f * b0.x; s[j][1] = 8.f * b0.y;
            s[j][2] = 8.f * b1.x; s[j][3] = 8.f * b1.y;
        }

        cp_wait0();
        __syncthreads();
        if (it < 31) load_kv((it + 1) & 1, k0 + 64);

        __half* Kh = KVbase + (it & 1) * KSTAGE;
        __half* Vh = Kh + KARR;

        // S += (Qh + Ql) · Kh^T   (2-pass; K rounded once)
#pragma unroll
        for (int kk = 0; kk < 4; kk++) {
#pragma unroll
            for (int np = 0; np < 4; np++) {
                int row = np * 16 + ((lane >> 4) << 3) + (lane & 7);
                int kof = kk * 16 + ((lane >> 3) & 1) * 8;
                uint32_t kh0, kh1, kh2, kh3;
                ldm_x4(kh0, kh1, kh2, kh3, smem_u32(&Kh[row * AST + kof]));
                mma16816h(s[2*np],   qH[kk], kh0, kh1);
                mma16816h(s[2*np+1], qH[kk], kh2, kh3);
                mma16816h(s[2*np],   qL[kk], kh0, kh1);
                mma16816h(s[2*np+1], qL[kk], kh2, kh3);
            }
        }

        // scale to true scores
#pragma unroll
        for (int j = 0; j < 8; j++) {
            s[j][0] *= 0.125f; s[j][1] *= 0.125f;
            s[j][2] *= 0.125f; s[j][3] *= 0.125f;
        }

        // online softmax
        float mxA = -INFINITY, mxB = -INFINITY;
#pragma unroll
        for (int j = 0; j < 8; j++) {
            mxA = fmaxf(mxA, fmaxf(s[j][0], s[j][1]));
            mxB = fmaxf(mxB, fmaxf(s[j][2], s[j][3]));
        }
        mxA = fmaxf(mxA, __shfl_xor_sync(0xffffffffu, mxA, 1));
        mxA = fmaxf(mxA, __shfl_xor_sync(0xffffffffu, mxA, 2));
        mxB = fmaxf(mxB, __shfl_xor_sync(0xffffffffu, mxB, 1));
        mxB = fmaxf(mxB, __shfl_xor_sync(0xffffffffu, mxB, 2));

        float mnA = fmaxf(mA, mxA), mnB = fmaxf(mB, mxB);
        float cA = __expf(mA - mnA), cB = __expf(mB - mnB);
        mA = mnA; mB = mnB;

        float sA = 0.f, sB = 0.f;
#pragma unroll
        for (int j = 0; j < 8; j++) {
            s[j][0] = __expf(s[j][0] - mnA);
            s[j][1] = __expf(s[j][1] - mnA);
            s[j][2] = __expf(s[j][2] - mnB);
            s[j][3] = __expf(s[j][3] - mnB);
            sA += s[j][0] + s[j][1];
            sB += s[j][2] + s[j][3];
        }
        sA += __shfl_xor_sync(0xffffffffu, sA, 1);
        sA += __shfl_xor_sync(0xffffffffu, sA, 2);
        sB += __shfl_xor_sync(0xffffffffu, sB, 1);
        sB += __shfl_xor_sync(0xffffffffu, sB, 2);
        lA = lA * cA + sA;
        lB = lB * cB + sB;

#pragma unroll
        for (int j = 0; j < 8; j++) {
            o[j][0] *= cA; o[j][1] *= cA; o[j][2] *= cB; o[j][3] *= cB;
        }

        // O += (Ph + Pl) · Vh  (2-pass; V rounded once; P exact in fp16 pair)
#pragma unroll
        for (int kk = 0; kk < 4; kk++) {
            uint32_t pH[4], pL[4];
            pack_hilo_h(s[2*kk][0],   s[2*kk][1],   pH[0], pL[0]);
            pack_hilo_h(s[2*kk][2],   s[2*kk][3],   pH[1], pL[1]);
            pack_hilo_h(s[2*kk+1][0], s[2*kk+1][1], pH[2], pL[2]);
            pack_hilo_h(s[2*kk+1][2], s[2*kk+1][3], pH[3], pL[3]);
#pragma unroll
            for (int np = 0; np < 4; np++) {
                int vrow = kk * 16 + ((lane >> 3) & 1) * 8 + (lane & 7);
                int vcol = np * 16 + (lane >> 4) * 8;
                uint32_t vh0, vh1, vh2, vh3;
                ldm_x4_t(vh0, vh1, vh2, vh3, smem_u32(&Vh[vrow * AST + vcol]));
                mma16816h(o[2*np],   pH, vh0, vh1);
                mma16816h(o[2*np+1], pH, vh2, vh3);
                mma16816h(o[2*np],   pL, vh0, vh1);
                mma16816h(o[2*np+1], pL, vh2, vh3);
            }
        }
    }

    // Epilogue: ctx bf16 hi/lo in [B, L, E] (out-proj consumes bf16)
    const float invA = 1.f / lA, invB = 1.f / lB;
    const int b = bh >> 4, h = bh & 15;
#pragma unroll
    for (int j = 0; j < 8; j++) {
        int d = j * 8 + colq;
        size_t eA = ((size_t)b * LSEQ + qrowA) * EMB + h * 64 + d;
        size_t eB = eA + (size_t)8 * EMB;
        uint32_t h01, l01, h23, l23;
        pack_hilo(o[j][0] * invA, o[j][1] * invA, h01, l01);
        pack_hilo(o[j][2] * invB, o[j][3] * invB, h23, l23);
        *(uint32_t*)(g_ch + eA) = h01;
        *(uint32_t*)(g_cl + eA) = l01;
        *(uint32_t*)(g_ch + eB) = h23;
        *(uint32_t*)(g_cl + eB) = l23;
    }
}

// ---------------------------------------------------------------------------
extern "C" void kernel_launch(void* const* d_in, const int* in_sizes, int n_in,
                              void* d_out, int out_size)
{
    const float* X     = (const float*)d_in[0];
    const float* keb   = (const float*)d_in[1];
    const float* w_in  = (const float*)d_in[2];
    const float* b_in  = (const float*)d_in[3];
    const float* w_out = (const float*)d_in[4];
    const float* b_out = (const float*)d_in[5];
    float* out = (float*)d_out;

    cudaFuncSetAttribute(gemm_mma<0>, cudaFuncAttributeMaxDynamicSharedMemorySize, GEMM_SMEM);
    cudaFuncSetAttribute(gemm_mma<1>, cudaFuncAttributeMaxDynamicSharedMemorySize, GEMM_SMEM);
    cudaFuncSetAttribute(attn_mma,    cudaFuncAttributeMaxDynamicSharedMemorySize, ATTN_SMEM);

    // 0) Split inputs into bf16 hi/lo
    cvt_hilo<<<4096, 256>>>(X,     0, M1*EMB/4);
    cvt_hilo<<<3072, 256>>>(w_in,  1, N1*EMB/4);
    cvt_hilo<<<1024, 256>>>(w_out, 2, EMB*EMB/4);

    // 1) QKV projection (bf16 3-pass; emits fp16 q hi/lo, k hi, v hi)
    gemm_mma<0><<<dim3(N1/128, M1/128), 256, GEMM_SMEM>>>(b_in, nullptr);

    // 2) Attention with additive ke_bias (fp16 2-pass QK and PV)
    attn_mma<<<dim3(LSEQ/128, BH), 256, ATTN_SMEM>>>(keb);

    // 3) Output projection (bf16 3-pass)
    gemm_mma<1><<<dim3(EMB/128, M1/128), 256, GEMM_SMEM>>>(b_out, out);
}

// round 9
// speedup vs baseline: 1.2111x; 1.2111x over previous
#include <cuda_runtime.h>
#include <cuda_bf16.h>
#include <cuda_fp16.h>
#include <math.h>
#include <stdint.h>

// Problem constants
#define BSZ 2
#define LSEQ 2048
#define EMB 1024
#define NH 16
#define DH 64
#define BH 32          // BSZ*NH
#define M1 4096        // BSZ*LSEQ
#define N1 3072        // 3*EMB

// Scratch (allocation-free) — all fp16 now
__device__ __half g_xh[M1*EMB],  g_xl[M1*EMB];     // X hi/lo
__device__ __half g_wi[N1*EMB];                    // W_in (single fp16)
__device__ __half g_wo[EMB*EMB];                   // W_out (single fp16)
__device__ __half g_ch[M1*EMB],  g_cl[M1*EMB];     // ctx hi/lo
__device__ __half g_qh[BH*LSEQ*DH], g_ql[BH*LSEQ*DH];
__device__ __half g_kh[BH*LSEQ*DH];
__device__ __half g_vh[BH*LSEQ*DH];

// ---------------------------------------------------------------------------
// PTX helpers
// ---------------------------------------------------------------------------
__device__ __forceinline__ uint32_t smem_u32(const void* p) {
    return (uint32_t)__cvta_generic_to_shared(p);
}
__device__ __forceinline__ void ldm_x4(uint32_t& a0, uint32_t& a1,
                                       uint32_t& a2, uint32_t& a3, uint32_t addr) {
    asm volatile("ldmatrix.sync.aligned.m8n8.x4.shared.b16 {%0,%1,%2,%3},[%4];\n"
                 : "=r"(a0), "=r"(a1), "=r"(a2), "=r"(a3) : "r"(addr));
}
__device__ __forceinline__ void ldm_x4_t(uint32_t& a0, uint32_t& a1,
                                         uint32_t& a2, uint32_t& a3, uint32_t addr) {
    asm volatile("ldmatrix.sync.aligned.m8n8.x4.trans.shared.b16 {%0,%1,%2,%3},[%4];\n"
                 : "=r"(a0), "=r"(a1), "=r"(a2), "=r"(a3) : "r"(addr));
}
// fp16 mma (fp32 accum)
__device__ __forceinline__ void mma16816h(float* c, const uint32_t* a,
                                          uint32_t b0, uint32_t b1) {
    asm volatile("mma.sync.aligned.m16n8k16.row.col.f32.f16.f16.f32 "
                 "{%0,%1,%2,%3},{%4,%5,%6,%7},{%8,%9},{%0,%1,%2,%3};\n"
                 : "+f"(c[0]), "+f"(c[1]), "+f"(c[2]), "+f"(c[3])
                 : "r"(a[0]), "r"(a[1]), "r"(a[2]), "r"(a[3]), "r"(b0), "r"(b1));
}
__device__ __forceinline__ void cp16(void* smem_ptr, const void* gptr) {
    asm volatile("cp.async.cg.shared.global [%0], [%1], 16;\n"
                 :: "r"(smem_u32(smem_ptr)), "l"(gptr));
}
__device__ __forceinline__ void cp_commit() {
    asm volatile("cp.async.commit_group;\n");
}
template<int N>
__device__ __forceinline__ void cp_wait() {
    asm volatile("cp.async.wait_group %0;\n" :: "n"(N));
}
// fp16 pack: v0 -> low half, v1 -> high half
__device__ __forceinline__ uint32_t packh(float v0, float v1) {
    __half2 h = __floats2half2_rn(v0, v1);
    return *(uint32_t*)&h;
}
__device__ __forceinline__ void pack_hilo_h(float v0, float v1,
                                            uint32_t& ph, uint32_t& pl) {
    ph = packh(v0, v1);
    __half2 h = *(__half2*)&ph;
    pl = packh(v0 - __half2float(h.x), v1 - __half2float(h.y));
}

// ---------------------------------------------------------------------------
// Prep: fp32 -> fp16. sel 0: X -> hi/lo. sel 1/2: W -> single fp16.
// ---------------------------------------------------------------------------
__global__ __launch_bounds__(256)
void cvt_prep(const float* __restrict__ src, int sel, int n4)
{
    int i = blockIdx.x * 256 + threadIdx.x;
    if (i >= n4) return;
    float4 v = ((const float4*)src)[i];
    if (sel == 0) {
        uint32_t h01, l01, h23, l23;
        pack_hilo_h(v.x, v.y, h01, l01);
        pack_hilo_h(v.z, v.w, h23, l23);
        ((uint32_t*)g_xh)[2*i]   = h01;  ((uint32_t*)g_xh)[2*i+1] = h23;
        ((uint32_t*)g_xl)[2*i]   = l01;  ((uint32_t*)g_xl)[2*i+1] = l23;
    } else {
        __half* dst = (sel == 1) ? g_wi : g_wo;
        ((uint32_t*)dst)[2*i]   = packh(v.x, v.y);
        ((uint32_t*)dst)[2*i+1] = packh(v.z, v.w);
    }
}

// ---------------------------------------------------------------------------
// GEMM: C[M,N] = (Ah+Al) @ W^T + bias. fp16 2-pass, 3-stage cp.async pipeline.
// BM=128, BN=128, BK=32, 256 threads (8 warps: 4m x 2n, warp = 32m x 64n).
// MODE 0: A=g_x*, W=g_wi; epilogue -> fp16: q hi/lo (UNSCALED), k hi, v hi
// MODE 1: A=g_c*, W=g_wo; epilogue writes fp32 C row-major
// ---------------------------------------------------------------------------
#define GST 40
#define GARR 5120           // 128*GST (halves)
#define GSTAGE 15360        // 3 arrays per stage (Ah, Al, W)
#define GEMM_SMEM (3*GSTAGE*2)  // 92160 bytes (3 stages)

template<int MODE>
__global__ __launch_bounds__(256, 2)
void gemm_mma(const float* __restrict__ bias, float* __restrict__ Cout)
{
    extern __shared__ __half smg[];
    const int tid = threadIdx.x, lane = tid & 31, w = tid >> 5;
    const int wm = w >> 1, wn = w & 1;
    const int m0 = blockIdx.y * 128, n0 = blockIdx.x * 128;

    const __half* Ahg = (MODE == 0) ? g_xh : g_ch;
    const __half* Alg = (MODE == 0) ? g_xl : g_cl;
    const __half* Wg  = (MODE == 0) ? g_wi : g_wo;

    const int lr = tid >> 1;            // 0..127
    const int lq = (tid & 1) * 16;      // elem offset 0/16
    const __half* pAh = Ahg + (size_t)(m0 + lr) * 1024 + lq;
    const __half* pAl = Alg + (size_t)(m0 + lr) * 1024 + lq;
    const __half* pW  = Wg  + (size_t)(n0 + lr) * 1024 + lq;

    auto load_stage = [&](int st, int k0) {
        __half* b = smg + st * GSTAGE + lr * GST + lq;
        cp16(b,          pAh + k0); cp16(b + 8,        pAh + k0 + 8);
        cp16(b + GARR,   pAl + k0); cp16(b + GARR + 8, pAl + k0 + 8);
        cp16(b + 2*GARR, pW  + k0); cp16(b + 2*GARR+8, pW  + k0 + 8);
        cp_commit();
    };

    float c[2][8][4];
#pragma unroll
    for (int a = 0; a < 2; a++)
#pragma unroll
        for (int b = 0; b < 8; b++)
#pragma unroll
            for (int d = 0; d < 4; d++) c[a][b][d] = 0.f;

    load_stage(0, 0);
    load_stage(1, 32);

    int st = 0;
    for (int it = 0; it < 32; it++) {
        if (it == 31) cp_wait<0>(); else cp_wait<1>();
        __syncthreads();
        if (it < 30) {
            int st2 = st + 2; if (st2 >= 3) st2 -= 3;
            load_stage(st2, (it + 2) * 32);
        }

        __half* Ah = smg + st * GSTAGE;
        __half* Al = Ah + GARR;
        __half* Ws = Ah + 2*GARR;

#pragma unroll
        for (int kk = 0; kk < 2; kk++) {
            uint32_t aH[2][4], aL[2][4];
#pragma unroll
            for (int mt = 0; mt < 2; mt++) {
                int row = wm * 32 + mt * 16 + (lane & 15);
                int kof = kk * 16 + ((lane >> 4) << 3);
                ldm_x4(aH[mt][0], aH[mt][1], aH[mt][2], aH[mt][3],
                       smem_u32(&Ah[row * GST + kof]));
                ldm_x4(aL[mt][0], aL[mt][1], aL[mt][2], aL[mt][3],
                       smem_u32(&Al[row * GST + kof]));
            }
#pragma unroll
            for (int np = 0; np < 4; np++) {
                int row = wn * 64 + np * 16 + ((lane >> 4) << 3) + (lane & 7);
                int kof = kk * 16 + ((lane >> 3) & 1) * 8;
                uint32_t w0, w1, w2, w3;
                ldm_x4(w0, w1, w2, w3, smem_u32(&Ws[row * GST + kof]));
                // pass H (4 independent accumulators)
                mma16816h(c[0][2*np],   aH[0], w0, w1);
                mma16816h(c[0][2*np+1], aH[0], w2, w3);
                mma16816h(c[1][2*np],   aH[1], w0, w1);
                mma16816h(c[1][2*np+1], aH[1], w2, w3);
                // pass L
                mma16816h(c[0][2*np],   aL[0], w0, w1);
                mma16816h(c[0][2*np+1], aL[0], w2, w3);
                mma16816h(c[1][2*np],   aL[1], w0, w1);
                mma16816h(c[1][2*np+1], aL[1], w2, w3);
            }
        }
        if (++st == 3) st = 0;
    }

    // Epilogue
    const int rA = lane >> 2, colq = (lane & 3) * 2;
#pragma unroll
    for (int mt = 0; mt < 2; mt++) {
#pragma unroll
        for (int np = 0; np < 4; np++) {
#pragma unroll
            for (int cc = 0; cc < 2; cc++) {
                int n = n0 + wn * 64 + np * 16 + cc * 8 + colq;
                int mrow = m0 + wm * 32 + mt * 16 + rA;
                float bv0 = bias[n], bv1 = bias[n + 1];
                float* cp = c[mt][2*np + cc];
                float v0 = cp[0] + bv0, v1 = cp[1] + bv1;
                float v2 = cp[2] + bv0, v3 = cp[3] + bv1;
                if (MODE == 0) {
                    int which = n >> 10;
                    int e = n & 1023, hh = e >> 6, d = e & 63;
                    int b = mrow >> 11;
                    size_t dA = (((size_t)(b * NH + hh)) * LSEQ + (mrow & 2047)) * DH + d;
                    size_t dB = dA + 8 * DH;
                    if (which == 0) {
                        // q: full precision fp16 hi/lo (no pre-scale)
                        uint32_t h01, l01, h23, l23;
                        pack_hilo_h(v0, v1, h01, l01);
                        pack_hilo_h(v2, v3, h23, l23);
                        *(uint32_t*)(g_qh + dA) = h01;
                        *(uint32_t*)(g_ql + dA) = l01;
                        *(uint32_t*)(g_qh + dB) = h23;
                        *(uint32_t*)(g_ql + dB) = l23;
                    } else {
                        __half* dst = (which == 1) ? g_kh : g_vh;
                        *(uint32_t*)(dst + dA) = packh(v0, v1);
                        *(uint32_t*)(dst + dB) = packh(v2, v3);
                    }
                } else {
                    *(float2*)(Cout + (size_t)mrow * EMB + n) = make_float2(v0, v1);
                    *(float2*)(Cout + (size_t)(mrow + 8) * EMB + n) = make_float2(v2, v3);
                }
            }
        }
    }
}

// ---------------------------------------------------------------------------
// Flash attention, fp16 2-pass: S = 0.125*((Qh+Ql)·Kh + 8*bias);
// O += (Ph+Pl)·Vh. K/V double-buffered via cp.async. 2 CTAs/SM.
// ---------------------------------------------------------------------------
#define AST 72
#define KARR 4608          // 64*AST
#define KSTAGE 9216        // 2 arrays (Kh, Vh)
#define ATTN_SMEM 73728

__global__ __launch_bounds__(256, 2)
void attn_mma(const float* __restrict__ keb)
{
    extern __shared__ __half sma[];
    __half* Qh = sma;
    __half* Ql = sma + 9216;
    __half* KVbase = sma + 18432;

    const int tid = threadIdx.x, lane = tid & 31, w = tid >> 5;
    const int bh = blockIdx.y;
    const int q0 = blockIdx.x * 128;
    const size_t hb = (size_t)bh * LSEQ * DH;
    const float* Bg = keb + (size_t)bh * LSEQ * LSEQ;

    const int lr = tid >> 2;           // 0..63
    const int lq = (tid & 3) * 16;     // 0,16,32,48
    const __half* pKh = g_kh + hb + (size_t)lr * 64 + lq;
    const __half* pVh = g_vh + hb + (size_t)lr * 64 + lq;

    auto load_kv = [&](int st, int k0) {
        __half* b = KVbase + st * KSTAGE + lr * AST + lq;
        size_t off = (size_t)k0 * 64;
        cp16(b,          pKh + off); cp16(b + 8,        pKh + off + 8);
        cp16(b + KARR,   pVh + off); cp16(b + KARR + 8, pVh + off + 8);
        cp_commit();
    };

    load_kv(0, 0);

    // Q tile -> smem (fp16 hi/lo)
#pragma unroll
    for (int i = 0; i < 4; i++) {
        int id = tid + i * 256;
        int r = id >> 3, c8 = (id & 7) * 8;
        size_t src = hb + (size_t)(q0 + r) * DH + c8;
        *(uint4*)&Qh[r * AST + c8] = *(const uint4*)(g_qh + src);
        *(uint4*)&Ql[r * AST + c8] = *(const uint4*)(g_ql + src);
    }
    __syncthreads();

    uint32_t qH[4][4], qL[4][4];
#pragma unroll
    for (int kk = 0; kk < 4; kk++) {
        int row = w * 16 + (lane & 15);
        int kof = kk * 16 + ((lane >> 4) << 3);
        ldm_x4(qH[kk][0], qH[kk][1], qH[kk][2], qH[kk][3], smem_u32(&Qh[row * AST + kof]));
        ldm_x4(qL[kk][0], qL[kk][1], qL[kk][2], qL[kk][3], smem_u32(&Ql[row * AST + kof]));
    }

    float o[8][4];
#pragma unroll
    for (int j = 0; j < 8; j++)
#pragma unroll
        for (int d = 0; d < 4; d++) o[j][d] = 0.f;
    float mA = -INFINITY, mB = -INFINITY, lA = 0.f, lB = 0.f;

    const int rA = lane >> 2, colq = (lane & 3) * 2;
    const int qrowA = q0 + w * 16 + rA;
    const float* Br0 = Bg + (size_t)qrowA * LSEQ + colq;
    const float* Br1 = Bg + (size_t)(qrowA + 8) * LSEQ + colq;

    for (int it = 0; it < 32; it++) {
        const int k0 = it * 64;

        // S init = 8*bias (post-mma scale 0.125 => net +bias)
        float s[8][4];
#pragma unroll
        for (int j = 0; j < 8; j++) {
            float2 b0 = *(const float2*)(Br0 + k0 + j * 8);
            float2 b1 = *(const float2*)(Br1 + k0 + j * 8);
            s[j][0] = 8.f * b0.x; s[j][1] = 8.f * b0.y;
            s[j][2] = 8.f * b1.x; s[j][3] = 8.f * b1.y;
        }

        cp_wait<0>();
        __syncthreads();
        if (it < 31) load_kv((it + 1) & 1, k0 + 64);

        __half* Kh = KVbase + (it & 1) * KSTAGE;
        __half* Vh = Kh + KARR;

        // S += (Qh + Ql) · Kh^T
#pragma unroll
        for (int kk = 0; kk < 4; kk++) {
#pragma unroll
            for (int np = 0; np < 4; np++) {
                int row = np * 16 + ((lane >> 4) << 3) + (lane & 7);
                int kof = kk * 16 + ((lane >> 3) & 1) * 8;
                uint32_t kh0, kh1, kh2, kh3;
                ldm_x4(kh0, kh1, kh2, kh3, smem_u32(&Kh[row * AST + kof]));
                mma16816h(s[2*np],   qH[kk], kh0, kh1);
                mma16816h(s[2*np+1], qH[kk], kh2, kh3);
                mma16816h(s[2*np],   qL[kk], kh0, kh1);
                mma16816h(s[2*np+1], qL[kk], kh2, kh3);
            }
        }

#pragma unroll
        for (int j = 0; j < 8; j++) {
            s[j][0] *= 0.125f; s[j][1] *= 0.125f;
            s[j][2] *= 0.125f; s[j][3] *= 0.125f;
        }

        // online softmax
        float mxA = -INFINITY, mxB = -INFINITY;
#pragma unroll
        for (int j = 0; j < 8; j++) {
            mxA = fmaxf(mxA, fmaxf(s[j][0], s[j][1]));
            mxB = fmaxf(mxB, fmaxf(s[j][2], s[j][3]));
        }
        mxA = fmaxf(mxA, __shfl_xor_sync(0xffffffffu, mxA, 1));
        mxA = fmaxf(mxA, __shfl_xor_sync(0xffffffffu, mxA, 2));
        mxB = fmaxf(mxB, __shfl_xor_sync(0xffffffffu, mxB, 1));
        mxB = fmaxf(mxB, __shfl_xor_sync(0xffffffffu, mxB, 2));

        float mnA = fmaxf(mA, mxA), mnB = fmaxf(mB, mxB);
        float cA = __expf(mA - mnA), cB = __expf(mB - mnB);
        mA = mnA; mB = mnB;

        float sA = 0.f, sB = 0.f;
#pragma unroll
        for (int j = 0; j < 8; j++) {
            s[j][0] = __expf(s[j][0] - mnA);
            s[j][1] = __expf(s[j][1] - mnA);
            s[j][2] = __expf(s[j][2] - mnB);
            s[j][3] = __expf(s[j][3] - mnB);
            sA += s[j][0] + s[j][1];
            sB += s[j][2] + s[j][3];
        }
        sA += __shfl_xor_sync(0xffffffffu, sA, 1);
        sA += __shfl_xor_sync(0xffffffffu, sA, 2);
        sB += __shfl_xor_sync(0xffffffffu, sB, 1);
        sB += __shfl_xor_sync(0xffffffffu, sB, 2);
        lA = lA * cA + sA;
        lB = lB * cB + sB;

#pragma unroll
        for (int j = 0; j < 8; j++) {
            o[j][0] *= cA; o[j][1] *= cA; o[j][2] *= cB; o[j][3] *= cB;
        }

        // O += (Ph + Pl) · Vh
#pragma unroll
        for (int kk = 0; kk < 4; kk++) {
            uint32_t pH[4], pL[4];
            pack_hilo_h(s[2*kk][0],   s[2*kk][1],   pH[0], pL[0]);
            pack_hilo_h(s[2*kk][2],   s[2*kk][3],   pH[1], pL[1]);
            pack_hilo_h(s[2*kk+1][0], s[2*kk+1][1], pH[2], pL[2]);
            pack_hilo_h(s[2*kk+1][2], s[2*kk+1][3], pH[3], pL[3]);
#pragma unroll
            for (int np = 0; np < 4; np++) {
                int vrow = kk * 16 + ((lane >> 3) & 1) * 8 + (lane & 7);
                int vcol = np * 16 + (lane >> 4) * 8;
                uint32_t vh0, vh1, vh2, vh3;
                ldm_x4_t(vh0, vh1, vh2, vh3, smem_u32(&Vh[vrow * AST + vcol]));
                mma16816h(o[2*np],   pH, vh0, vh1);
                mma16816h(o[2*np+1], pH, vh2, vh3);
                mma16816h(o[2*np],   pL, vh0, vh1);
                mma16816h(o[2*np+1], pL, vh2, vh3);
            }
        }
    }

    // Epilogue: ctx fp16 hi/lo in [B, L, E]
    const float invA = 1.f / lA, invB = 1.f / lB;
    const int b = bh >> 4, h = bh & 15;
#pragma unroll
    for (int j = 0; j < 8; j++) {
        int d = j * 8 + colq;
        size_t eA = ((size_t)b * LSEQ + qrowA) * EMB + h * 64 + d;
        size_t eB = eA + (size_t)8 * EMB;
        uint32_t h01, l01, h23, l23;
        pack_hilo_h(o[j][0] * invA, o[j][1] * invA, h01, l01);
        pack_hilo_h(o[j][2] * invB, o[j][3] * invB, h23, l23);
        *(uint32_t*)(g_ch + eA) = h01;
        *(uint32_t*)(g_cl + eA) = l01;
        *(uint32_t*)(g_ch + eB) = h23;
        *(uint32_t*)(g_cl + eB) = l23;
    }
}

// ---------------------------------------------------------------------------
extern "C" void kernel_launch(void* const* d_in, const int* in_sizes, int n_in,
                              void* d_out, int out_size)
{
    const float* X     = (const float*)d_in[0];
    const float* keb   = (const float*)d_in[1];
    const float* w_in  = (const float*)d_in[2];
    const float* b_in  = (const float*)d_in[3];
    const float* w_out = (const float*)d_in[4];
    const float* b_out = (const float*)d_in[5];
    float* out = (float*)d_out;

    cudaFuncSetAttribute(gemm_mma<0>, cudaFuncAttributeMaxDynamicSharedMemorySize, GEMM_SMEM);
    cudaFuncSetAttribute(gemm_mma<1>, cudaFuncAttributeMaxDynamicSharedMemorySize, GEMM_SMEM);
    cudaFuncSetAttribute(attn_mma,    cudaFuncAttributeMaxDynamicSharedMemorySize, ATTN_SMEM);

    // 0) fp16 prep: X hi/lo, W_in, W_out
    cvt_prep<<<4096, 256>>>(X,     0, M1*EMB/4);
    cvt_prep<<<3072, 256>>>(w_in,  1, N1*EMB/4);
    cvt_prep<<<1024, 256>>>(w_out, 2, EMB*EMB/4);

    // 1) QKV projection (fp16 2-pass)
    gemm_mma<0><<<dim3(N1/128, M1/128), 256, GEMM_SMEM>>>(b_in, nullptr);

    // 2) Attention with additive ke_bias (fp16 2-pass QK and PV)
    attn_mma<<<dim3(LSEQ/128, BH), 256, ATTN_SMEM>>>(keb);

    // 3) Output projection (fp16 2-pass)
    gemm_mma<1><<<dim3(EMB/128, M1/128), 256, GEMM_SMEM>>>(b_out, out);
}

// round 10
// speedup vs baseline: 2.0105x; 1.6600x over previous
#include <cuda_runtime.h>
#include <cuda_bf16.h>
#include <cuda_fp16.h>
#include <math.h>
#include <stdint.h>

// Problem constants
#define BSZ 2
#define LSEQ 2048
#define EMB 1024
#define NH 16
#define DH 64
#define BH 32          // BSZ*NH
#define M1 4096        // BSZ*LSEQ
#define N1 3072        // 3*EMB

// Scratch (allocation-free) — single fp16 everywhere except P (register hi/lo)
__device__ __half g_x[M1*EMB];
__device__ __half g_wi[N1*EMB];
__device__ __half g_wo[EMB*EMB];
__device__ __half g_c[M1*EMB];
__device__ __half g_q[BH*LSEQ*DH];
__device__ __half g_k[BH*LSEQ*DH];
__device__ __half g_v[BH*LSEQ*DH];

// ---------------------------------------------------------------------------
// PTX helpers
// ---------------------------------------------------------------------------
__device__ __forceinline__ uint32_t smem_u32(const void* p) {
    return (uint32_t)__cvta_generic_to_shared(p);
}
__device__ __forceinline__ void ldm_x4(uint32_t& a0, uint32_t& a1,
                                       uint32_t& a2, uint32_t& a3, uint32_t addr) {
    asm volatile("ldmatrix.sync.aligned.m8n8.x4.shared.b16 {%0,%1,%2,%3},[%4];\n"
                 : "=r"(a0), "=r"(a1), "=r"(a2), "=r"(a3) : "r"(addr));
}
__device__ __forceinline__ void ldm_x4_t(uint32_t& a0, uint32_t& a1,
                                         uint32_t& a2, uint32_t& a3, uint32_t addr) {
    asm volatile("ldmatrix.sync.aligned.m8n8.x4.trans.shared.b16 {%0,%1,%2,%3},[%4];\n"
                 : "=r"(a0), "=r"(a1), "=r"(a2), "=r"(a3) : "r"(addr));
}
// fp16 mma (fp32 accum)
__device__ __forceinline__ void mma16816h(float* c, const uint32_t* a,
                                          uint32_t b0, uint32_t b1) {
    asm volatile("mma.sync.aligned.m16n8k16.row.col.f32.f16.f16.f32 "
                 "{%0,%1,%2,%3},{%4,%5,%6,%7},{%8,%9},{%0,%1,%2,%3};\n"
                 : "+f"(c[0]), "+f"(c[1]), "+f"(c[2]), "+f"(c[3])
                 : "r"(a[0]), "r"(a[1]), "r"(a[2]), "r"(a[3]), "r"(b0), "r"(b1));
}
__device__ __forceinline__ void cp16(void* smem_ptr, const void* gptr) {
    asm volatile("cp.async.cg.shared.global [%0], [%1], 16;\n"
                 :: "r"(smem_u32(smem_ptr)), "l"(gptr));
}
__device__ __forceinline__ void cp_commit() {
    asm volatile("cp.async.commit_group;\n");
}
template<int N>
__device__ __forceinline__ void cp_wait() {
    asm volatile("cp.async.wait_group %0;\n" :: "n"(N));
}
__device__ __forceinline__ uint32_t packh(float v0, float v1) {
    __half2 h = __floats2half2_rn(v0, v1);
    return *(uint32_t*)&h;
}
__device__ __forceinline__ void pack_hilo_h(float v0, float v1,
                                            uint32_t& ph, uint32_t& pl) {
    ph = packh(v0, v1);
    __half2 h = *(__half2*)&ph;
    pl = packh(v0 - __half2float(h.x), v1 - __half2float(h.y));
}

// ---------------------------------------------------------------------------
// Prep: fp32 -> single fp16
// ---------------------------------------------------------------------------
__global__ __launch_bounds__(256)
void cvt_prep(const float* __restrict__ src, int sel, int n4)
{
    int i = blockIdx.x * 256 + threadIdx.x;
    if (i >= n4) return;
    __half* dst = (sel == 0) ? g_x : (sel == 1) ? g_wi : g_wo;
    float4 v = ((const float4*)src)[i];
    ((uint32_t*)dst)[2*i]   = packh(v.x, v.y);
    ((uint32_t*)dst)[2*i+1] = packh(v.z, v.w);
}

// ---------------------------------------------------------------------------
// GEMM: C[M,N] = A @ W^T + bias, single-pass fp16 mma.
// BM=128, BN=128, BK=64, 256 threads (8 warps: 4m x 2n, warp = 32m x 64n).
// 3-stage cp.async pipeline.
// MODE 0: A=g_x, W=g_wi; epilogue -> q (UNSCALED), k, v fp16 in [BH,L,D]
// MODE 1: A=g_c, W=g_wo; epilogue writes fp32 C row-major
// ---------------------------------------------------------------------------
#define GST 72
#define GARR (128*GST)          // 9216 halves per array
#define GSTAGE (2*GARR)         // A + W
#define GEMM_SMEM (3*GSTAGE*2)  // 110592 bytes (3 stages)

template<int MODE>
__global__ __launch_bounds__(256, 2)
void gemm_mma(const float* __restrict__ bias, float* __restrict__ Cout)
{
    extern __shared__ __half smg[];
    const int tid = threadIdx.x, lane = tid & 31, w = tid >> 5;
    const int wm = w >> 1, wn = w & 1;
    const int m0 = blockIdx.y * 128, n0 = blockIdx.x * 128;

    const __half* Ag = (MODE == 0) ? g_x  : g_c;
    const __half* Wg = (MODE == 0) ? g_wi : g_wo;

    // Loader: row = tid>>1 (0..127), half-row of 32 elems (64B = 4 cp16)
    const int lr = tid >> 1;
    const int lq = (tid & 1) * 32;
    const __half* pA = Ag + (size_t)(m0 + lr) * 1024 + lq;
    const __half* pW = Wg + (size_t)(n0 + lr) * 1024 + lq;

    auto load_stage = [&](int st, int k0) {
        __half* b = smg + st * GSTAGE + lr * GST + lq;
        cp16(b,      pA + k0);      cp16(b + 8,        pA + k0 + 8);
        cp16(b + 16, pA + k0 + 16); cp16(b + 24,       pA + k0 + 24);
        __half* b2 = b + GARR;
        cp16(b2,      pW + k0);      cp16(b2 + 8,      pW + k0 + 8);
        cp16(b2 + 16, pW + k0 + 16); cp16(b2 + 24,     pW + k0 + 24);
        cp_commit();
    };

    float c[2][8][4];
#pragma unroll
    for (int a = 0; a < 2; a++)
#pragma unroll
        for (int b = 0; b < 8; b++)
#pragma unroll
            for (int d = 0; d < 4; d++) c[a][b][d] = 0.f;

    const int arow = wm * 32 + (lane & 15);
    const int akof = (lane >> 4) << 3;
    const int wrow = wn * 64 + ((lane >> 4) << 3) + (lane & 7);
    const int wkof = ((lane >> 3) & 1) * 8;

    load_stage(0, 0);
    load_stage(1, 64);

    int st = 0;
    for (int it = 0; it < 16; it++) {
        if (it == 15) cp_wait<0>(); else cp_wait<1>();
        __syncthreads();
        if (it < 14) {
            int st2 = st + 2; if (st2 >= 3) st2 -= 3;
            load_stage(st2, (it + 2) * 64);
        }

        __half* As = smg + st * GSTAGE;
        __half* Ws = As + GARR;

#pragma unroll
        for (int kk = 0; kk < 4; kk++) {
            uint32_t aF[2][4];
#pragma unroll
            for (int mt = 0; mt < 2; mt++) {
                int off = (arow + mt * 16) * GST + kk * 16 + akof;
                ldm_x4(aF[mt][0], aF[mt][1], aF[mt][2], aF[mt][3],
                       smem_u32(&As[off]));
            }
#pragma unroll
            for (int np = 0; np < 4; np++) {
                int off = (wrow + np * 16) * GST + kk * 16 + wkof;
                uint32_t w0, w1, w2, w3;
                ldm_x4(w0, w1, w2, w3, smem_u32(&Ws[off]));
                mma16816h(c[0][2*np],   aF[0], w0, w1);
                mma16816h(c[0][2*np+1], aF[0], w2, w3);
                mma16816h(c[1][2*np],   aF[1], w0, w1);
                mma16816h(c[1][2*np+1], aF[1], w2, w3);
            }
        }
        if (++st == 3) st = 0;
    }

    // Epilogue
    const int rA = lane >> 2, colq = (lane & 3) * 2;
#pragma unroll
    for (int mt = 0; mt < 2; mt++) {
#pragma unroll
        for (int np = 0; np < 4; np++) {
#pragma unroll
            for (int cc = 0; cc < 2; cc++) {
                int n = n0 + wn * 64 + np * 16 + cc * 8 + colq;
                int mrow = m0 + wm * 32 + mt * 16 + rA;
                float bv0 = bias[n], bv1 = bias[n + 1];
                float* cp = c[mt][2*np + cc];
                float v0 = cp[0] + bv0, v1 = cp[1] + bv1;
                float v2 = cp[2] + bv0, v3 = cp[3] + bv1;
                if (MODE == 0) {
                    int which = n >> 10;
                    int e = n & 1023, hh = e >> 6, d = e & 63;
                    int b = mrow >> 11;
                    size_t dA = (((size_t)(b * NH + hh)) * LSEQ + (mrow & 2047)) * DH + d;
                    size_t dB = dA + 8 * DH;
                    __half* dst = (which == 0) ? g_q : (which == 1) ? g_k : g_v;
                    *(uint32_t*)(dst + dA) = packh(v0, v1);
                    *(uint32_t*)(dst + dB) = packh(v2, v3);
                } else {
                    *(float2*)(Cout + (size_t)mrow * EMB + n) = make_float2(v0, v1);
                    *(float2*)(Cout + (size_t)(mrow + 8) * EMB + n) = make_float2(v2, v3);
                }
            }
        }
    }
}

// ---------------------------------------------------------------------------
// Flash attention, fp16: S = 0.125*(q·k + 8*bias) (1-pass QK);
// O += (Ph+Pl)·V (P exact hi/lo in registers, V rounded once).
// K/V double-buffered via cp.async. Grid (L/128, BH), 256 thr, 2 CTAs/SM.
// ---------------------------------------------------------------------------
#define AST 72
#define KARR 4608          // 64*AST
#define KSTAGE 9216        // Kh + Vh
#define ATTN_SMEM 55296    // (9216 Q + 2*9216 KV) * 2B

__global__ __launch_bounds__(256, 2)
void attn_mma(const float* __restrict__ keb)
{
    extern __shared__ __half sma[];
    __half* Qs = sma;                 // 128 x AST
    __half* KVbase = sma + 9216;

    const int tid = threadIdx.x, lane = tid & 31, w = tid >> 5;
    const int bh = blockIdx.y;
    const int q0 = blockIdx.x * 128;
    const size_t hb = (size_t)bh * LSEQ * DH;
    const float* Bg = keb + (size_t)bh * LSEQ * LSEQ;

    const int lr = tid >> 2;           // 0..63
    const int lq = (tid & 3) * 16;     // 0,16,32,48
    const __half* pK = g_k + hb + (size_t)lr * 64 + lq;
    const __half* pV = g_v + hb + (size_t)lr * 64 + lq;

    auto load_kv = [&](int st, int k0) {
        __half* b = KVbase + st * KSTAGE + lr * AST + lq;
        size_t off = (size_t)k0 * 64;
        cp16(b,        pK + off); cp16(b + 8,        pK + off + 8);
        cp16(b + KARR, pV + off); cp16(b + KARR + 8, pV + off + 8);
        cp_commit();
    };

    load_kv(0, 0);

    // Q tile -> smem (single fp16)
#pragma unroll
    for (int i = 0; i < 4; i++) {
        int id = tid + i * 256;
        int r = id >> 3, c8 = (id & 7) * 8;
        *(uint4*)&Qs[r * AST + c8] = *(const uint4*)(g_q + hb + (size_t)(q0 + r) * DH + c8);
    }
    __syncthreads();

    uint32_t qF[4][4];
#pragma unroll
    for (int kk = 0; kk < 4; kk++) {
        int row = w * 16 + (lane & 15);
        int kof = kk * 16 + ((lane >> 4) << 3);
        ldm_x4(qF[kk][0], qF[kk][1], qF[kk][2], qF[kk][3], smem_u32(&Qs[row * AST + kof]));
    }

    float o[8][4];
#pragma unroll
    for (int j = 0; j < 8; j++)
#pragma unroll
        for (int d = 0; d < 4; d++) o[j][d] = 0.f;
    float mA = -INFINITY, mB = -INFINITY, lA = 0.f, lB = 0.f;

    const int rA = lane >> 2, colq = (lane & 3) * 2;
    const int qrowA = q0 + w * 16 + rA;
    const float* Br0 = Bg + (size_t)qrowA * LSEQ + colq;
    const float* Br1 = Bg + (size_t)(qrowA + 8) * LSEQ + colq;

    for (int it = 0; it < 32; it++) {
        const int k0 = it * 64;

        // S init = 8*bias (post-mma scale 0.125 => net +bias)
        float s[8][4];
#pragma unroll
        for (int j = 0; j < 8; j++) {
            float2 b0 = *(const float2*)(Br0 + k0 + j * 8);
            float2 b1 = *(const float2*)(Br1 + k0 + j * 8);
            s[j][0] = 8.f * b0.x; s[j][1] = 8.f * b0.y;
            s[j][2] = 8.f * b1.x; s[j][3] = 8.f * b1.y;
        }

        cp_wait<0>();
        __syncthreads();
        if (it < 31) load_kv((it + 1) & 1, k0 + 64);

        __half* Kh = KVbase + (it & 1) * KSTAGE;
        __half* Vh = Kh + KARR;

        // S += q · k^T (1-pass)
#pragma unroll
        for (int kk = 0; kk < 4; kk++) {
#pragma unroll
            for (int np = 0; np < 4; np++) {
                int row = np * 16 + ((lane >> 4) << 3) + (lane & 7);
                int kof = kk * 16 + ((lane >> 3) & 1) * 8;
                uint32_t kh0, kh1, kh2, kh3;
                ldm_x4(kh0, kh1, kh2, kh3, smem_u32(&Kh[row * AST + kof]));
                mma16816h(s[2*np],   qF[kk], kh0, kh1);
                mma16816h(s[2*np+1], qF[kk], kh2, kh3);
            }
        }

#pragma unroll
        for (int j = 0; j < 8; j++) {
            s[j][0] *= 0.125f; s[j][1] *= 0.125f;
            s[j][2] *= 0.125f; s[j][3] *= 0.125f;
        }

        // online softmax
        float mxA = -INFINITY, mxB = -INFINITY;
#pragma unroll
        for (int j = 0; j < 8; j++) {
            mxA = fmaxf(mxA, fmaxf(s[j][0], s[j][1]));
            mxB = fmaxf(mxB, fmaxf(s[j][2], s[j][3]));
        }
        mxA = fmaxf(mxA, __shfl_xor_sync(0xffffffffu, mxA, 1));
        mxA = fmaxf(mxA, __shfl_xor_sync(0xffffffffu, mxA, 2));
        mxB = fmaxf(mxB, __shfl_xor_sync(0xffffffffu, mxB, 1));
        mxB = fmaxf(mxB, __shfl_xor_sync(0xffffffffu, mxB, 2));

        float mnA = fmaxf(mA, mxA), mnB = fmaxf(mB, mxB);
        float cA = __expf(mA - mnA), cB = __expf(mB - mnB);
        mA = mnA; mB = mnB;

        float sA = 0.f, sB = 0.f;
#pragma unroll
        for (int j = 0; j < 8; j++) {
            s[j][0] = __expf(s[j][0] - mnA);
            s[j][1] = __expf(s[j][1] - mnA);
            s[j][2] = __expf(s[j][2] - mnB);
            s[j][3] = __expf(s[j][3] - mnB);
            sA += s[j][0] + s[j][1];
            sB += s[j][2] + s[j][3];
        }
        sA += __shfl_xor_sync(0xffffffffu, sA, 1);
        sA += __shfl_xor_sync(0xffffffffu, sA, 2);
        sB += __shfl_xor_sync(0xffffffffu, sB, 1);
        sB += __shfl_xor_sync(0xffffffffu, sB, 2);
        lA = lA * cA + sA;
        lB = lB * cB + sB;

#pragma unroll
        for (int j = 0; j < 8; j++) {
            o[j][0] *= cA; o[j][1] *= cA; o[j][2] *= cB; o[j][3] *= cB;
        }

        // O += (Ph + Pl) · V
#pragma unroll
        for (int kk = 0; kk < 4; kk++) {
            uint32_t pH[4], pL[4];
            pack_hilo_h(s[2*kk][0],   s[2*kk][1],   pH[0], pL[0]);
            pack_hilo_h(s[2*kk][2],   s[2*kk][3],   pH[1], pL[1]);
            pack_hilo_h(s[2*kk+1][0], s[2*kk+1][1], pH[2], pL[2]);
            pack_hilo_h(s[2*kk+1][2], s[2*kk+1][3], pH[3], pL[3]);
#pragma unroll
            for (int np = 0; np < 4; np++) {
                int vrow = kk * 16 + ((lane >> 3) & 1) * 8 + (lane & 7);
                int vcol = np * 16 + (lane >> 4) * 8;
                uint32_t vh0, vh1, vh2, vh3;
                ldm_x4_t(vh0, vh1, vh2, vh3, smem_u32(&Vh[vrow * AST + vcol]));
                mma16816h(o[2*np],   pH, vh0, vh1);
                mma16816h(o[2*np+1], pH, vh2, vh3);
                mma16816h(o[2*np],   pL, vh0, vh1);
                mma16816h(o[2*np+1], pL, vh2, vh3);
            }
        }
    }

    // Epilogue: ctx single fp16 in [B, L, E]
    const float invA = 1.f / lA, invB = 1.f / lB;
    const int b = bh >> 4, h = bh & 15;
#pragma unroll
    for (int j = 0; j < 8; j++) {
        int d = j * 8 + colq;
        size_t eA = ((size_t)b * LSEQ + qrowA) * EMB + h * 64 + d;
        size_t eB = eA + (size_t)8 * EMB;
        *(uint32_t*)(g_c + eA) = packh(o[j][0] * invA, o[j][1] * invA);
        *(uint32_t*)(g_c + eB) = packh(o[j][2] * invB, o[j][3] * invB);
    }
}

// ---------------------------------------------------------------------------
extern "C" void kernel_launch(void* const* d_in, const int* in_sizes, int n_in,
                              void* d_out, int out_size)
{
    const float* X     = (const float*)d_in[0];
    const float* keb   = (const float*)d_in[1];
    const float* w_in  = (const float*)d_in[2];
    const float* b_in  = (const float*)d_in[3];
    const float* w_out = (const float*)d_in[4];
    const float* b_out = (const float*)d_in[5];
    float* out = (float*)d_out;

    cudaFuncSetAttribute(gemm_mma<0>, cudaFuncAttributeMaxDynamicSharedMemorySize, GEMM_SMEM);
    cudaFuncSetAttribute(gemm_mma<1>, cudaFuncAttributeMaxDynamicSharedMemorySize, GEMM_SMEM);
    cudaFuncSetAttribute(attn_mma,    cudaFuncAttributeMaxDynamicSharedMemorySize, ATTN_SMEM);

    // 0) fp16 prep
    cvt_prep<<<4096, 256>>>(X,     0, M1*EMB/4);
    cvt_prep<<<3072, 256>>>(w_in,  1, N1*EMB/4);
    cvt_prep<<<1024, 256>>>(w_out, 2, EMB*EMB/4);

    // 1) QKV projection (fp16 1-pass)
    gemm_mma<0><<<dim3(N1/128, M1/128), 256, GEMM_SMEM>>>(b_in, nullptr);

    // 2) Attention with additive ke_bias (1-pass QK, 2-pass PV)
    attn_mma<<<dim3(LSEQ/128, BH), 256, ATTN_SMEM>>>(keb);

    // 3) Output projection (fp16 1-pass)
    gemm_mma<1><<<dim3(EMB/128, M1/128), 256, GEMM_SMEM>>>(b_out, out);
}

// round 11
// speedup vs baseline: 2.2262x; 1.1073x over previous
#include <cuda_runtime.h>
#include <cuda_fp16.h>
#include <math.h>
#include <stdint.h>

// Problem constants
#define BSZ 2
#define LSEQ 2048
#define EMB 1024
#define NH 16
#define DH 64
#define BH 32          // BSZ*NH
#define M1 4096        // BSZ*LSEQ
#define N1 3072        // 3*EMB

// Scratch (allocation-free) — single fp16 everywhere
__device__ __half g_x[M1*EMB];
__device__ __half g_wi[N1*EMB];
__device__ __half g_wo[EMB*EMB];
__device__ __half g_c[M1*EMB];
__device__ __half g_q[BH*LSEQ*DH];
__device__ __half g_k[BH*LSEQ*DH];
__device__ __half g_v[BH*LSEQ*DH];

// ---------------------------------------------------------------------------
// PTX helpers
// ---------------------------------------------------------------------------
__device__ __forceinline__ uint32_t smem_u32(const void* p) {
    return (uint32_t)__cvta_generic_to_shared(p);
}
__device__ __forceinline__ void ldm_x4(uint32_t& a0, uint32_t& a1,
                                       uint32_t& a2, uint32_t& a3, uint32_t addr) {
    asm volatile("ldmatrix.sync.aligned.m8n8.x4.shared.b16 {%0,%1,%2,%3},[%4];\n"
                 : "=r"(a0), "=r"(a1), "=r"(a2), "=r"(a3) : "r"(addr));
}
__device__ __forceinline__ void ldm_x4_t(uint32_t& a0, uint32_t& a1,
                                         uint32_t& a2, uint32_t& a3, uint32_t addr) {
    asm volatile("ldmatrix.sync.aligned.m8n8.x4.trans.shared.b16 {%0,%1,%2,%3},[%4];\n"
                 : "=r"(a0), "=r"(a1), "=r"(a2), "=r"(a3) : "r"(addr));
}
// fp16 mma (fp32 accum)
__device__ __forceinline__ void mma16816h(float* c, const uint32_t* a,
                                          uint32_t b0, uint32_t b1) {
    asm volatile("mma.sync.aligned.m16n8k16.row.col.f32.f16.f16.f32 "
                 "{%0,%1,%2,%3},{%4,%5,%6,%7},{%8,%9},{%0,%1,%2,%3};\n"
                 : "+f"(c[0]), "+f"(c[1]), "+f"(c[2]), "+f"(c[3])
                 : "r"(a[0]), "r"(a[1]), "r"(a[2]), "r"(a[3]), "r"(b0), "r"(b1));
}
__device__ __forceinline__ void cp16(void* smem_ptr, const void* gptr) {
    asm volatile("cp.async.cg.shared.global [%0], [%1], 16;\n"
                 :: "r"(smem_u32(smem_ptr)), "l"(gptr));
}
__device__ __forceinline__ void cp_commit() {
    asm volatile("cp.async.commit_group;\n");
}
template<int N>
__device__ __forceinline__ void cp_wait() {
    asm volatile("cp.async.wait_group %0;\n" :: "n"(N));
}
__device__ __forceinline__ uint32_t packh(float v0, float v1) {
    __half2 h = __floats2half2_rn(v0, v1);
    return *(uint32_t*)&h;
}

// ---------------------------------------------------------------------------
// Prep: fp32 -> single fp16
// ---------------------------------------------------------------------------
__global__ __launch_bounds__(256)
void cvt_prep(const float* __restrict__ src, int sel, int n4)
{
    int i = blockIdx.x * 256 + threadIdx.x;
    if (i >= n4) return;
    __half* dst = (sel == 0) ? g_x : (sel == 1) ? g_wi : g_wo;
    float4 v = ((const float4*)src)[i];
    ((uint32_t*)dst)[2*i]   = packh(v.x, v.y);
    ((uint32_t*)dst)[2*i+1] = packh(v.z, v.w);
}

// ---------------------------------------------------------------------------
// GEMM: C[M,N] = A @ W^T + bias, single-pass fp16 mma.
// BM=128, BN=128, BK=64, 256 threads (8 warps: 4m x 2n, warp = 32m x 64n).
// 3-stage cp.async pipeline.
// MODE 0: A=g_x, W=g_wi; epilogue -> q (UNSCALED), k, v fp16 in [BH,L,D]
// MODE 1: A=g_c, W=g_wo; epilogue writes fp32 C row-major
// ---------------------------------------------------------------------------
#define GST 72
#define GARR (128*GST)          // 9216 halves per array
#define GSTAGE (2*GARR)         // A + W
#define GEMM_SMEM (3*GSTAGE*2)  // 110592 bytes (3 stages)

template<int MODE>
__global__ __launch_bounds__(256, 2)
void gemm_mma(const float* __restrict__ bias, float* __restrict__ Cout)
{
    extern __shared__ __half smg[];
    const int tid = threadIdx.x, lane = tid & 31, w = tid >> 5;
    const int wm = w >> 1, wn = w & 1;
    const int m0 = blockIdx.y * 128, n0 = blockIdx.x * 128;

    const __half* Ag = (MODE == 0) ? g_x  : g_c;
    const __half* Wg = (MODE == 0) ? g_wi : g_wo;

    const int lr = tid >> 1;
    const int lq = (tid & 1) * 32;
    const __half* pA = Ag + (size_t)(m0 + lr) * 1024 + lq;
    const __half* pW = Wg + (size_t)(n0 + lr) * 1024 + lq;

    auto load_stage = [&](int st, int k0) {
        __half* b = smg + st * GSTAGE + lr * GST + lq;
        cp16(b,      pA + k0);      cp16(b + 8,        pA + k0 + 8);
        cp16(b + 16, pA + k0 + 16); cp16(b + 24,       pA + k0 + 24);
        __half* b2 = b + GARR;
        cp16(b2,      pW + k0);      cp16(b2 + 8,      pW + k0 + 8);
        cp16(b2 + 16, pW + k0 + 16); cp16(b2 + 24,     pW + k0 + 24);
        cp_commit();
    };

    float c[2][8][4];
#pragma unroll
    for (int a = 0; a < 2; a++)
#pragma unroll
        for (int b = 0; b < 8; b++)
#pragma unroll
            for (int d = 0; d < 4; d++) c[a][b][d] = 0.f;

    const int arow = wm * 32 + (lane & 15);
    const int akof = (lane >> 4) << 3;
    const int wrow = wn * 64 + ((lane >> 4) << 3) + (lane & 7);
    const int wkof = ((lane >> 3) & 1) * 8;

    load_stage(0, 0);
    load_stage(1, 64);

    int st = 0;
    for (int it = 0; it < 16; it++) {
        if (it == 15) cp_wait<0>(); else cp_wait<1>();
        __syncthreads();
        if (it < 14) {
            int st2 = st + 2; if (st2 >= 3) st2 -= 3;
            load_stage(st2, (it + 2) * 64);
        }

        __half* As = smg + st * GSTAGE;
        __half* Ws = As + GARR;

#pragma unroll
        for (int kk = 0; kk < 4; kk++) {
            uint32_t aF[2][4];
#pragma unroll
            for (int mt = 0; mt < 2; mt++) {
                int off = (arow + mt * 16) * GST + kk * 16 + akof;
                ldm_x4(aF[mt][0], aF[mt][1], aF[mt][2], aF[mt][3],
                       smem_u32(&As[off]));
            }
#pragma unroll
            for (int np = 0; np < 4; np++) {
                int off = (wrow + np * 16) * GST + kk * 16 + wkof;
                uint32_t w0, w1, w2, w3;
                ldm_x4(w0, w1, w2, w3, smem_u32(&Ws[off]));
                mma16816h(c[0][2*np],   aF[0], w0, w1);
                mma16816h(c[0][2*np+1], aF[0], w2, w3);
                mma16816h(c[1][2*np],   aF[1], w0, w1);
                mma16816h(c[1][2*np+1], aF[1], w2, w3);
            }
        }
        if (++st == 3) st = 0;
    }

    // Epilogue
    const int rA = lane >> 2, colq = (lane & 3) * 2;
#pragma unroll
    for (int mt = 0; mt < 2; mt++) {
#pragma unroll
        for (int np = 0; np < 4; np++) {
#pragma unroll
            for (int cc = 0; cc < 2; cc++) {
                int n = n0 + wn * 64 + np * 16 + cc * 8 + colq;
                int mrow = m0 + wm * 32 + mt * 16 + rA;
                float bv0 = bias[n], bv1 = bias[n + 1];
                float* cp = c[mt][2*np + cc];
                float v0 = cp[0] + bv0, v1 = cp[1] + bv1;
                float v2 = cp[2] + bv0, v3 = cp[3] + bv1;
                if (MODE == 0) {
                    int which = n >> 10;
                    int e = n & 1023, hh = e >> 6, d = e & 63;
                    int b = mrow >> 11;
                    size_t dA = (((size_t)(b * NH + hh)) * LSEQ + (mrow & 2047)) * DH + d;
                    size_t dB = dA + 8 * DH;
                    __half* dst = (which == 0) ? g_q : (which == 1) ? g_k : g_v;
                    *(uint32_t*)(dst + dA) = packh(v0, v1);
                    *(uint32_t*)(dst + dB) = packh(v2, v3);
                } else {
                    *(float2*)(Cout + (size_t)mrow * EMB + n) = make_float2(v0, v1);
                    *(float2*)(Cout + (size_t)(mrow + 8) * EMB + n) = make_float2(v2, v3);
                }
            }
        }
    }
}

// ---------------------------------------------------------------------------
// Flash attention, fp16 1-pass QK and 1-pass PV.
// Scores kept in RAW units (q·k + 8*bias); softmax folds the 0.125 scale
// into the exp argument via FMA (scale-invariant max tracking).
// K/V double-buffered via cp.async. Grid (L/128, BH), 256 thr, 2 CTAs/SM.
// ---------------------------------------------------------------------------
#define AST 72
#define KARR 4608          // 64*AST
#define KSTAGE 9216        // K + V
#define ATTN_SMEM 55296    // (9216 Q + 2*9216 KV) * 2B

__global__ __launch_bounds__(256, 2)
void attn_mma(const float* __restrict__ keb)
{
    extern __shared__ __half sma[];
    __half* Qs = sma;                 // 128 x AST
    __half* KVbase = sma + 9216;

    const int tid = threadIdx.x, lane = tid & 31, w = tid >> 5;
    const int bh = blockIdx.y;
    const int q0 = blockIdx.x * 128;
    const size_t hb = (size_t)bh * LSEQ * DH;
    const float* Bg = keb + (size_t)bh * LSEQ * LSEQ;

    const int lr = tid >> 2;           // 0..63
    const int lq = (tid & 3) * 16;     // 0,16,32,48
    const __half* pK = g_k + hb + (size_t)lr * 64 + lq;
    const __half* pV = g_v + hb + (size_t)lr * 64 + lq;

    auto load_kv = [&](int st, int k0) {
        __half* b = KVbase + st * KSTAGE + lr * AST + lq;
        size_t off = (size_t)k0 * 64;
        cp16(b,        pK + off); cp16(b + 8,        pK + off + 8);
        cp16(b + KARR, pV + off); cp16(b + KARR + 8, pV + off + 8);
        cp_commit();
    };

    load_kv(0, 0);

    // Q tile -> smem
#pragma unroll
    for (int i = 0; i < 4; i++) {
        int id = tid + i * 256;
        int r = id >> 3, c8 = (id & 7) * 8;
        *(uint4*)&Qs[r * AST + c8] = *(const uint4*)(g_q + hb + (size_t)(q0 + r) * DH + c8);
    }
    __syncthreads();

    uint32_t qF[4][4];
#pragma unroll
    for (int kk = 0; kk < 4; kk++) {
        int row = w * 16 + (lane & 15);
        int kof = kk * 16 + ((lane >> 4) << 3);
        ldm_x4(qF[kk][0], qF[kk][1], qF[kk][2], qF[kk][3], smem_u32(&Qs[row * AST + kof]));
    }

    float o[8][4];
#pragma unroll
    for (int j = 0; j < 8; j++)
#pragma unroll
        for (int d = 0; d < 4; d++) o[j][d] = 0.f;
    // raw-unit running max (scores kept at 8x scale until the exp)
    float mA = -INFINITY, mB = -INFINITY, lA = 0.f, lB = 0.f;

    const int rA = lane >> 2, colq = (lane & 3) * 2;
    const int qrowA = q0 + w * 16 + rA;
    const float* Br0 = Bg + (size_t)qrowA * LSEQ + colq;
    const float* Br1 = Bg + (size_t)(qrowA + 8) * LSEQ + colq;

    for (int it = 0; it < 32; it++) {
        const int k0 = it * 64;

        // S init = 8*bias (raw units; exp applies the 1/8)
        float s[8][4];
#pragma unroll
        for (int j = 0; j < 8; j++) {
            float2 b0 = *(const float2*)(Br0 + k0 + j * 8);
            float2 b1 = *(const float2*)(Br1 + k0 + j * 8);
            s[j][0] = 8.f * b0.x; s[j][1] = 8.f * b0.y;
            s[j][2] = 8.f * b1.x; s[j][3] = 8.f * b1.y;
        }

        cp_wait<0>();
        __syncthreads();
        if (it < 31) load_kv((it + 1) & 1, k0 + 64);

        __half* Kh = KVbase + (it & 1) * KSTAGE;
        __half* Vh = Kh + KARR;

        // S += q · k^T (1-pass)
#pragma unroll
        for (int kk = 0; kk < 4; kk++) {
#pragma unroll
            for (int np = 0; np < 4; np++) {
                int row = np * 16 + ((lane >> 4) << 3) + (lane & 7);
                int kof = kk * 16 + ((lane >> 3) & 1) * 8;
                uint32_t kh0, kh1, kh2, kh3;
                ldm_x4(kh0, kh1, kh2, kh3, smem_u32(&Kh[row * AST + kof]));
                mma16816h(s[2*np],   qF[kk], kh0, kh1);
                mma16816h(s[2*np+1], qF[kk], kh2, kh3);
            }
        }

        // online softmax in raw units; exp argument = 0.125*s - 0.125*m
        float mxA = -INFINITY, mxB = -INFINITY;
#pragma unroll
        for (int j = 0; j < 8; j++) {
            mxA = fmaxf(mxA, fmaxf(s[j][0], s[j][1]));
            mxB = fmaxf(mxB, fmaxf(s[j][2], s[j][3]));
        }
        mxA = fmaxf(mxA, __shfl_xor_sync(0xffffffffu, mxA, 1));
        mxA = fmaxf(mxA, __shfl_xor_sync(0xffffffffu, mxA, 2));
        mxB = fmaxf(mxB, __shfl_xor_sync(0xffffffffu, mxB, 1));
        mxB = fmaxf(mxB, __shfl_xor_sync(0xffffffffu, mxB, 2));

        float mnA = fmaxf(mA, mxA), mnB = fmaxf(mB, mxB);
        float cA = __expf((mA - mnA) * 0.125f);
        float cB = __expf((mB - mnB) * 0.125f);
        mA = mnA; mB = mnB;
        const float mA125 = mnA * 0.125f, mB125 = mnB * 0.125f;

        float sA = 0.f, sB = 0.f;
#pragma unroll
        for (int j = 0; j < 8; j++) {
            s[j][0] = __expf(fmaf(s[j][0], 0.125f, -mA125));
            s[j][1] = __expf(fmaf(s[j][1], 0.125f, -mA125));
            s[j][2] = __expf(fmaf(s[j][2], 0.125f, -mB125));
            s[j][3] = __expf(fmaf(s[j][3], 0.125f, -mB125));
            sA += s[j][0] + s[j][1];
            sB += s[j][2] + s[j][3];
        }
        sA += __shfl_xor_sync(0xffffffffu, sA, 1);
        sA += __shfl_xor_sync(0xffffffffu, sA, 2);
        sB += __shfl_xor_sync(0xffffffffu, sB, 1);
        sB += __shfl_xor_sync(0xffffffffu, sB, 2);
        lA = lA * cA + sA;
        lB = lB * cB + sB;

#pragma unroll
        for (int j = 0; j < 8; j++) {
            o[j][0] *= cA; o[j][1] *= cA; o[j][2] *= cB; o[j][3] *= cB;
        }

        // O += P · V (1-pass; P rounded once to fp16)
#pragma unroll
        for (int kk = 0; kk < 4; kk++) {
            uint32_t pF[4];
            pF[0] = packh(s[2*kk][0],   s[2*kk][1]);
            pF[1] = packh(s[2*kk][2],   s[2*kk][3]);
            pF[2] = packh(s[2*kk+1][0], s[2*kk+1][1]);
            pF[3] = packh(s[2*kk+1][2], s[2*kk+1][3]);
#pragma unroll
            for (int np = 0; np < 4; np++) {
                int vrow = kk * 16 + ((lane >> 3) & 1) * 8 + (lane & 7);
                int vcol = np * 16 + (lane >> 4) * 8;
                uint32_t vh0, vh1, vh2, vh3;
                ldm_x4_t(vh0, vh1, vh2, vh3, smem_u32(&Vh[vrow * AST + vcol]));
                mma16816h(o[2*np],   pF, vh0, vh1);
                mma16816h(o[2*np+1], pF, vh2, vh3);
            }
        }
    }

    // Epilogue: ctx single fp16 in [B, L, E]
    const float invA = 1.f / lA, invB = 1.f / lB;
    const int b = bh >> 4, h = bh & 15;
#pragma unroll
    for (int j = 0; j < 8; j++) {
        int d = j * 8 + colq;
        size_t eA = ((size_t)b * LSEQ + qrowA) * EMB + h * 64 + d;
        size_t eB = eA + (size_t)8 * EMB;
        *(uint32_t*)(g_c + eA) = packh(o[j][0] * invA, o[j][1] * invA);
        *(uint32_t*)(g_c + eB) = packh(o[j][2] * invB, o[j][3] * invB);
    }
}

// ---------------------------------------------------------------------------
extern "C" void kernel_launch(void* const* d_in, const int* in_sizes, int n_in,
                              void* d_out, int out_size)
{
    const float* X     = (const float*)d_in[0];
    const float* keb   = (const float*)d_in[1];
    const float* w_in  = (const float*)d_in[2];
    const float* b_in  = (const float*)d_in[3];
    const float* w_out = (const float*)d_in[4];
    const float* b_out = (const float*)d_in[5];
    float* out = (float*)d_out;

    cudaFuncSetAttribute(gemm_mma<0>, cudaFuncAttributeMaxDynamicSharedMemorySize, GEMM_SMEM);
    cudaFuncSetAttribute(gemm_mma<1>, cudaFuncAttributeMaxDynamicSharedMemorySize, GEMM_SMEM);
    cudaFuncSetAttribute(attn_mma,    cudaFuncAttributeMaxDynamicSharedMemorySize, ATTN_SMEM);

    // 0) fp16 prep
    cvt_prep<<<4096, 256>>>(X,     0, M1*EMB/4);
    cvt_prep<<<3072, 256>>>(w_in,  1, N1*EMB/4);
    cvt_prep<<<1024, 256>>>(w_out, 2, EMB*EMB/4);

    // 1) QKV projection (fp16 1-pass)
    gemm_mma<0><<<dim3(N1/128, M1/128), 256, GEMM_SMEM>>>(b_in, nullptr);

    // 2) Attention with additive ke_bias (1-pass QK, 1-pass PV)
    attn_mma<<<dim3(LSEQ/128, BH), 256, ATTN_SMEM>>>(keb);

    // 3) Output projection (fp16 1-pass)
    gemm_mma<1><<<dim3(EMB/128, M1/128), 256, GEMM_SMEM>>>(b_out, out);
}

// round 12
// speedup vs baseline: 2.2516x; 1.0114x over previous
#include <cuda_runtime.h>
#include <cuda_fp16.h>
#include <math.h>
#include <stdint.h>

// Problem constants
#define BSZ 2
#define LSEQ 2048
#define EMB 1024
#define NH 16
#define DH 64
#define BH 32          // BSZ*NH
#define M1 4096        // BSZ*LSEQ
#define N1 3072        // 3*EMB

// Scratch (allocation-free) — single fp16 everywhere
__device__ __half g_x[M1*EMB];
__device__ __half g_wi[N1*EMB];
__device__ __half g_wo[EMB*EMB];
__device__ __half g_c[M1*EMB];
__device__ __half g_q[BH*LSEQ*DH];
__device__ __half g_k[BH*LSEQ*DH];
__device__ __half g_v[BH*LSEQ*DH];

// ---------------------------------------------------------------------------
// PTX helpers
// ---------------------------------------------------------------------------
__device__ __forceinline__ uint32_t smem_u32(const void* p) {
    return (uint32_t)__cvta_generic_to_shared(p);
}
__device__ __forceinline__ void ldm_x4(uint32_t& a0, uint32_t& a1,
                                       uint32_t& a2, uint32_t& a3, uint32_t addr) {
    asm volatile("ldmatrix.sync.aligned.m8n8.x4.shared.b16 {%0,%1,%2,%3},[%4];\n"
                 : "=r"(a0), "=r"(a1), "=r"(a2), "=r"(a3) : "r"(addr));
}
__device__ __forceinline__ void ldm_x4_t(uint32_t& a0, uint32_t& a1,
                                         uint32_t& a2, uint32_t& a3, uint32_t addr) {
    asm volatile("ldmatrix.sync.aligned.m8n8.x4.trans.shared.b16 {%0,%1,%2,%3},[%4];\n"
                 : "=r"(a0), "=r"(a1), "=r"(a2), "=r"(a3) : "r"(addr));
}
// fp16 mma (fp32 accum)
__device__ __forceinline__ void mma16816h(float* c, const uint32_t* a,
                                          uint32_t b0, uint32_t b1) {
    asm volatile("mma.sync.aligned.m16n8k16.row.col.f32.f16.f16.f32 "
                 "{%0,%1,%2,%3},{%4,%5,%6,%7},{%8,%9},{%0,%1,%2,%3};\n"
                 : "+f"(c[0]), "+f"(c[1]), "+f"(c[2]), "+f"(c[3])
                 : "r"(a[0]), "r"(a[1]), "r"(a[2]), "r"(a[3]), "r"(b0), "r"(b1));
}
__device__ __forceinline__ void cp16(void* smem_ptr, const void* gptr) {
    asm volatile("cp.async.cg.shared.global [%0], [%1], 16;\n"
                 :: "r"(smem_u32(smem_ptr)), "l"(gptr));
}
__device__ __forceinline__ void cp_commit() {
    asm volatile("cp.async.commit_group;\n");
}
template<int N>
__device__ __forceinline__ void cp_wait() {
    asm volatile("cp.async.wait_group %0;\n" :: "n"(N));
}
__device__ __forceinline__ uint32_t packh(float v0, float v1) {
    __half2 h = __floats2half2_rn(v0, v1);
    return *(uint32_t*)&h;
}

// ---------------------------------------------------------------------------
// Prep: fp32 -> single fp16, all three tensors in one launch
// ---------------------------------------------------------------------------
#define NX4  1048576   // M1*EMB/4
#define NWI4 786432    // N1*EMB/4
#define NWO4 262144    // EMB*EMB/4

__global__ __launch_bounds__(256)
void cvt_prep(const float* __restrict__ X, const float* __restrict__ wi,
              const float* __restrict__ wo)
{
    int i = blockIdx.x * 256 + threadIdx.x;
    const float* src;
    __half* dst;
    int j;
    if (i < NX4)              { src = X;  dst = g_x;  j = i; }
    else if (i < NX4 + NWI4)  { src = wi; dst = g_wi; j = i - NX4; }
    else                      { src = wo; dst = g_wo; j = i - NX4 - NWI4; }
    float4 v = ((const float4*)src)[j];
    ((uint32_t*)dst)[2*j]   = packh(v.x, v.y);
    ((uint32_t*)dst)[2*j+1] = packh(v.z, v.w);
}

// ---------------------------------------------------------------------------
// GEMM: C[M,N] = A @ W^T + bias, single-pass fp16 mma.
// BM=128, BN=64, BK=64, 256 threads (8 warps: 4m x 2n, warp = 32m x 32n).
// 2-stage cp.async pipeline; 3 CTAs/SM (regs capped at 84 via launch_bounds).
// MODE 0: A=g_x, W=g_wi; epilogue -> q (UNSCALED), k, v fp16 in [BH,L,D]
// MODE 1: A=g_c, W=g_wo; epilogue writes fp32 C row-major
// ---------------------------------------------------------------------------
#define GST 72
#define GA_OFF 9216             // 128*GST halves (A block)
#define GSTAGE 13824            // + 64*GST (W block)
#define GEMM_SMEM (2*GSTAGE*2)  // 55296 bytes, 2 stages

template<int MODE>
__global__ __launch_bounds__(256, 3)
void gemm_mma(const float* __restrict__ bias, float* __restrict__ Cout)
{
    extern __shared__ __half smg[];
    const int tid = threadIdx.x, lane = tid & 31, w = tid >> 5;
    const int wm = w >> 1, wn = w & 1;
    const int m0 = blockIdx.y * 128, n0 = blockIdx.x * 64;

    const __half* Ag = (MODE == 0) ? g_x  : g_c;
    const __half* Wg = (MODE == 0) ? g_wi : g_wo;

    // A loader: 128 rows, 32 halves (4 cp16) per thread
    const int lr = tid >> 1;
    const int lq = (tid & 1) * 32;
    // W loader: 64 rows, 16 halves (2 cp16) per thread
    const int wr = tid >> 2;
    const int wq = (tid & 3) * 16;
    const __half* pA = Ag + (size_t)(m0 + lr) * 1024 + lq;
    const __half* pW = Wg + (size_t)(n0 + wr) * 1024 + wq;

    auto load_stage = [&](int st, int k0) {
        __half* b = smg + st * GSTAGE + lr * GST + lq;
        cp16(b,      pA + k0);      cp16(b + 8,  pA + k0 + 8);
        cp16(b + 16, pA + k0 + 16); cp16(b + 24, pA + k0 + 24);
        __half* b2 = smg + st * GSTAGE + GA_OFF + wr * GST + wq;
        cp16(b2, pW + k0); cp16(b2 + 8, pW + k0 + 8);
        cp_commit();
    };

    float c[2][4][4];
#pragma unroll
    for (int a = 0; a < 2; a++)
#pragma unroll
        for (int b = 0; b < 4; b++)
#pragma unroll
            for (int d = 0; d < 4; d++) c[a][b][d] = 0.f;

    const int arow = wm * 32 + (lane & 15);
    const int akof = (lane >> 4) << 3;
    const int wrow = wn * 32 + ((lane >> 4) << 3) + (lane & 7);
    const int wkof = ((lane >> 3) & 1) * 8;

    load_stage(0, 0);

    for (int it = 0; it < 16; it++) {
        cp_wait<0>();
        __syncthreads();
        if (it < 15) load_stage((it + 1) & 1, (it + 1) * 64);

        __half* As = smg + (it & 1) * GSTAGE;
        __half* Ws = As + GA_OFF;

#pragma unroll
        for (int kk = 0; kk < 4; kk++) {
            uint32_t aF[2][4];
#pragma unroll
            for (int mt = 0; mt < 2; mt++) {
                int off = (arow + mt * 16) * GST + kk * 16 + akof;
                ldm_x4(aF[mt][0], aF[mt][1], aF[mt][2], aF[mt][3],
                       smem_u32(&As[off]));
            }
#pragma unroll
            for (int np = 0; np < 2; np++) {
                int off = (wrow + np * 16) * GST + kk * 16 + wkof;
                uint32_t w0, w1, w2, w3;
                ldm_x4(w0, w1, w2, w3, smem_u32(&Ws[off]));
                mma16816h(c[0][2*np],   aF[0], w0, w1);
                mma16816h(c[0][2*np+1], aF[0], w2, w3);
                mma16816h(c[1][2*np],   aF[1], w0, w1);
                mma16816h(c[1][2*np+1], aF[1], w2, w3);
            }
        }
    }

    // Epilogue
    const int rA = lane >> 2, colq = (lane & 3) * 2;
#pragma unroll
    for (int mt = 0; mt < 2; mt++) {
#pragma unroll
        for (int np = 0; np < 2; np++) {
#pragma unroll
            for (int cc = 0; cc < 2; cc++) {
                int n = n0 + wn * 32 + np * 16 + cc * 8 + colq;
                int mrow = m0 + wm * 32 + mt * 16 + rA;
                float bv0 = bias[n], bv1 = bias[n + 1];
                float* cp = c[mt][2*np + cc];
                float v0 = cp[0] + bv0, v1 = cp[1] + bv1;
                float v2 = cp[2] + bv0, v3 = cp[3] + bv1;
                if (MODE == 0) {
                    int which = n >> 10;
                    int e = n & 1023, hh = e >> 6, d = e & 63;
                    int b = mrow >> 11;
                    size_t dA = (((size_t)(b * NH + hh)) * LSEQ + (mrow & 2047)) * DH + d;
                    size_t dB = dA + 8 * DH;
                    __half* dst = (which == 0) ? g_q : (which == 1) ? g_k : g_v;
                    *(uint32_t*)(dst + dA) = packh(v0, v1);
                    *(uint32_t*)(dst + dB) = packh(v2, v3);
                } else {
                    *(float2*)(Cout + (size_t)mrow * EMB + n) = make_float2(v0, v1);
                    *(float2*)(Cout + (size_t)(mrow + 8) * EMB + n) = make_float2(v2, v3);
                }
            }
        }
    }
}

// ---------------------------------------------------------------------------
// Flash attention, fp16 1-pass QK and 1-pass PV (unchanged from R11).
// ---------------------------------------------------------------------------
#define AST 72
#define KARR 4608          // 64*AST
#define KSTAGE 9216        // K + V
#define ATTN_SMEM 55296    // (9216 Q + 2*9216 KV) * 2B

__global__ __launch_bounds__(256, 2)
void attn_mma(const float* __restrict__ keb)
{
    extern __shared__ __half sma[];
    __half* Qs = sma;                 // 128 x AST
    __half* KVbase = sma + 9216;

    const int tid = threadIdx.x, lane = tid & 31, w = tid >> 5;
    const int bh = blockIdx.y;
    const int q0 = blockIdx.x * 128;
    const size_t hb = (size_t)bh * LSEQ * DH;
    const float* Bg = keb + (size_t)bh * LSEQ * LSEQ;

    const int lr = tid >> 2;           // 0..63
    const int lq = (tid & 3) * 16;     // 0,16,32,48
    const __half* pK = g_k + hb + (size_t)lr * 64 + lq;
    const __half* pV = g_v + hb + (size_t)lr * 64 + lq;

    auto load_kv = [&](int st, int k0) {
        __half* b = KVbase + st * KSTAGE + lr * AST + lq;
        size_t off = (size_t)k0 * 64;
        cp16(b,        pK + off); cp16(b + 8,        pK + off + 8);
        cp16(b + KARR, pV + off); cp16(b + KARR + 8, pV + off + 8);
        cp_commit();
    };

    load_kv(0, 0);

    // Q tile -> smem
#pragma unroll
    for (int i = 0; i < 4; i++) {
        int id = tid + i * 256;
        int r = id >> 3, c8 = (id & 7) * 8;
        *(uint4*)&Qs[r * AST + c8] = *(const uint4*)(g_q + hb + (size_t)(q0 + r) * DH + c8);
    }
    __syncthreads();

    uint32_t qF[4][4];
#pragma unroll
    for (int kk = 0; kk < 4; kk++) {
        int row = w * 16 + (lane & 15);
        int kof = kk * 16 + ((lane >> 4) << 3);
        ldm_x4(qF[kk][0], qF[kk][1], qF[kk][2], qF[kk][3], smem_u32(&Qs[row * AST + kof]));
    }

    float o[8][4];
#pragma unroll
    for (int j = 0; j < 8; j++)
#pragma unroll
        for (int d = 0; d < 4; d++) o[j][d] = 0.f;
    float mA = -INFINITY, mB = -INFINITY, lA = 0.f, lB = 0.f;

    const int rA = lane >> 2, colq = (lane & 3) * 2;
    const int qrowA = q0 + w * 16 + rA;
    const float* Br0 = Bg + (size_t)qrowA * LSEQ + colq;
    const float* Br1 = Bg + (size_t)(qrowA + 8) * LSEQ + colq;

    for (int it = 0; it < 32; it++) {
        const int k0 = it * 64;

        // S init = 8*bias (raw units; exp applies the 1/8)
        float s[8][4];
#pragma unroll
        for (int j = 0; j < 8; j++) {
            float2 b0 = *(const float2*)(Br0 + k0 + j * 8);
            float2 b1 = *(const float2*)(Br1 + k0 + j * 8);
            s[j][0] = 8.f * b0.x; s[j][1] = 8.f * b0.y;
            s[j][2] = 8.f * b1.x; s[j][3] = 8.f * b1.y;
        }

        cp_wait<0>();
        __syncthreads();
        if (it < 31) load_kv((it + 1) & 1, k0 + 64);

        __half* Kh = KVbase + (it & 1) * KSTAGE;
        __half* Vh = Kh + KARR;

        // S += q · k^T (1-pass)
#pragma unroll
        for (int kk = 0; kk < 4; kk++) {
#pragma unroll
            for (int np = 0; np < 4; np++) {
                int row = np * 16 + ((lane >> 4) << 3) + (lane & 7);
                int kof = kk * 16 + ((lane >> 3) & 1) * 8;
                uint32_t kh0, kh1, kh2, kh3;
                ldm_x4(kh0, kh1, kh2, kh3, smem_u32(&Kh[row * AST + kof]));
                mma16816h(s[2*np],   qF[kk], kh0, kh1);
                mma16816h(s[2*np+1], qF[kk], kh2, kh3);
            }
        }

        // online softmax in raw units; exp argument = 0.125*s - 0.125*m
        float mxA = -INFINITY, mxB = -INFINITY;
#pragma unroll
        for (int j = 0; j < 8; j++) {
            mxA = fmaxf(mxA, fmaxf(s[j][0], s[j][1]));
            mxB = fmaxf(mxB, fmaxf(s[j][2], s[j][3]));
        }
        mxA = fmaxf(mxA, __shfl_xor_sync(0xffffffffu, mxA, 1));
        mxA = fmaxf(mxA, __shfl_xor_sync(0xffffffffu, mxA, 2));
        mxB = fmaxf(mxB, __shfl_xor_sync(0xffffffffu, mxB, 1));
        mxB = fmaxf(mxB, __shfl_xor_sync(0xffffffffu, mxB, 2));

        float mnA = fmaxf(mA, mxA), mnB = fmaxf(mB, mxB);
        float cA = __expf((mA - mnA) * 0.125f);
        float cB = __expf((mB - mnB) * 0.125f);
        mA = mnA; mB = mnB;
        const float mA125 = mnA * 0.125f, mB125 = mnB * 0.125f;

        float sA = 0.f, sB = 0.f;
#pragma unroll
        for (int j = 0; j < 8; j++) {
            s[j][0] = __expf(fmaf(s[j][0], 0.125f, -mA125));
            s[j][1] = __expf(fmaf(s[j][1], 0.125f, -mA125));
            s[j][2] = __expf(fmaf(s[j][2], 0.125f, -mB125));
            s[j][3] = __expf(fmaf(s[j][3], 0.125f, -mB125));
            sA += s[j][0] + s[j][1];
            sB += s[j][2] + s[j][3];
        }
        sA += __shfl_xor_sync(0xffffffffu, sA, 1);
        sA += __shfl_xor_sync(0xffffffffu, sA, 2);
        sB += __shfl_xor_sync(0xffffffffu, sB, 1);
        sB += __shfl_xor_sync(0xffffffffu, sB, 2);
        lA = lA * cA + sA;
        lB = lB * cB + sB;

#pragma unroll
        for (int j = 0; j < 8; j++) {
            o[j][0] *= cA; o[j][1] *= cA; o[j][2] *= cB; o[j][3] *= cB;
        }

        // O += P · V (1-pass; P rounded once to fp16)
#pragma unroll
        for (int kk = 0; kk < 4; kk++) {
            uint32_t pF[4];
            pF[0] = packh(s[2*kk][0],   s[2*kk][1]);
            pF[1] = packh(s[2*kk][2],   s[2*kk][3]);
            pF[2] = packh(s[2*kk+1][0], s[2*kk+1][1]);
            pF[3] = packh(s[2*kk+1][2], s[2*kk+1][3]);
#pragma unroll
            for (int np = 0; np < 4; np++) {
                int vrow = kk * 16 + ((lane >> 3) & 1) * 8 + (lane & 7);
                int vcol = np * 16 + (lane >> 4) * 8;
                uint32_t vh0, vh1, vh2, vh3;
                ldm_x4_t(vh0, vh1, vh2, vh3, smem_u32(&Vh[vrow * AST + vcol]));
                mma16816h(o[2*np],   pF, vh0, vh1);
                mma16816h(o[2*np+1], pF, vh2, vh3);
            }
        }
    }

    // Epilogue: ctx single fp16 in [B, L, E]
    const float invA = 1.f / lA, invB = 1.f / lB;
    const int b = bh >> 4, h = bh & 15;
#pragma unroll
    for (int j = 0; j < 8; j++) {
        int d = j * 8 + colq;
        size_t eA = ((size_t)b * LSEQ + qrowA) * EMB + h * 64 + d;
        size_t eB = eA + (size_t)8 * EMB;
        *(uint32_t*)(g_c + eA) = packh(o[j][0] * invA, o[j][1] * invA);
        *(uint32_t*)(g_c + eB) = packh(o[j][2] * invB, o[j][3] * invB);
    }
}

// ---------------------------------------------------------------------------
extern "C" void kernel_launch(void* const* d_in, const int* in_sizes, int n_in,
                              void* d_out, int out_size)
{
    const float* X     = (const float*)d_in[0];
    const float* keb   = (const float*)d_in[1];
    const float* w_in  = (const float*)d_in[2];
    const float* b_in  = (const float*)d_in[3];
    const float* w_out = (const float*)d_in[4];
    const float* b_out = (const float*)d_in[5];
    float* out = (float*)d_out;

    cudaFuncSetAttribute(gemm_mma<0>, cudaFuncAttributeMaxDynamicSharedMemorySize, GEMM_SMEM);
    cudaFuncSetAttribute(gemm_mma<1>, cudaFuncAttributeMaxDynamicSharedMemorySize, GEMM_SMEM);
    cudaFuncSetAttribute(attn_mma,    cudaFuncAttributeMaxDynamicSharedMemorySize, ATTN_SMEM);

    // 0) fp16 prep (one launch)
    cvt_prep<<<(NX4 + NWI4 + NWO4) / 256, 256>>>(X, w_in, w_out);

    // 1) QKV projection (fp16 1-pass, 3 CTAs/SM)
    gemm_mma<0><<<dim3(N1/64, M1/128), 256, GEMM_SMEM>>>(b_in, nullptr);

    // 2) Attention with additive ke_bias (1-pass QK, 1-pass PV)
    attn_mma<<<dim3(LSEQ/128, BH), 256, ATTN_SMEM>>>(keb);

    // 3) Output projection (fp16 1-pass, 3 CTAs/SM)
    gemm_mma<1><<<dim3(EMB/64, M1/128), 256, GEMM_SMEM>>>(b_out, out);
}